// round 13
// baseline (speedup 1.0000x reference)
#include <cuda_runtime.h>
#include <cuda_fp16.h>
#include <stdint.h>
#include <math.h>

#define BATCH  4
#define NHEADS 16
#define HEAD   64
#define SEQ    2048
#define EMBED  1024
#define QKVN   3072
#define NTOK   (BATCH * SEQ)   // 8192
#define HPAD   72              // half-row pad: 144B, ldmatrix phase conflict-free

// ---------------- scratch (device globals: allocation-free) ----------------
__device__ __half g_qh[BATCH * NHEADS * SEQ * HEAD];  // [B,H,S,D] fp16, pre-scaled
__device__ __half g_kh[BATCH * NHEADS * SEQ * HEAD];  // [B,H,S,D] fp16
__device__ __half g_vh[BATCH * NHEADS * HEAD * SEQ];  // [B,H,D,S] fp16 (transposed)
__device__ __half g_attnh[BATCH * SEQ * EMBED];       // [B,S,H*D] fp16
__device__ __half g_xh[NTOK * EMBED];                 // X fp16
__device__ __half g_wqkvh[QKVN * EMBED];              // packed [n][k] fp16
__device__ __half g_woh[EMBED * EMBED];               // Wo [e][f] fp16

// ---------------- helpers ----------------
__device__ __forceinline__ void mma16(float* c,
                                      uint32_t a0, uint32_t a1, uint32_t a2, uint32_t a3,
                                      uint32_t b0, uint32_t b1) {
    asm volatile(
        "mma.sync.aligned.m16n8k16.row.col.f32.f16.f16.f32 "
        "{%0,%1,%2,%3}, {%4,%5,%6,%7}, {%8,%9}, {%0,%1,%2,%3};"
        : "+f"(c[0]), "+f"(c[1]), "+f"(c[2]), "+f"(c[3])
        : "r"(a0), "r"(a1), "r"(a2), "r"(a3), "r"(b0), "r"(b1));
}

__device__ __forceinline__ void ldsm4(uint32_t* r, const void* p) {
    uint32_t a = (uint32_t)__cvta_generic_to_shared(p);
    asm volatile("ldmatrix.sync.aligned.m8n8.x4.shared.b16 {%0,%1,%2,%3}, [%4];"
                 : "=r"(r[0]), "=r"(r[1]), "=r"(r[2]), "=r"(r[3]) : "r"(a));
}

__device__ __forceinline__ void cp16(void* smem, const void* gmem) {
    uint32_t sa = (uint32_t)__cvta_generic_to_shared(smem);
    asm volatile("cp.async.cg.shared.global [%0], [%1], 16;" :: "r"(sa), "l"(gmem));
}
#define CP_COMMIT() asm volatile("cp.async.commit_group;")
#define CP_WAIT0()  asm volatile("cp.async.wait_group 0;")
#define CP_WAIT1()  asm volatile("cp.async.wait_group 1;")

__device__ __forceinline__ uint32_t h2u(__half2 h) { return *(uint32_t*)&h; }

// smem sizes (bytes)
#define GEMM_SMEM (2 * 2 * 128 * HPAD * 2)                       // 73728
#define ATTN_SMEM ((128 * 72 + 3 * 64 * 72 + 3 * 64 * 72) * 2)  // 73728

// ============================================================================
// Prep kernels
// ============================================================================
__global__ __launch_bounds__(256) void x2h_kernel(const float* __restrict__ x) {
    int i = (blockIdx.x * 256 + threadIdx.x) * 4;
    float4 v = *(const float4*)(x + i);
    *(__half2*)(g_xh + i)     = __floats2half2_rn(v.x, v.y);
    *(__half2*)(g_xh + i + 2) = __floats2half2_rn(v.z, v.w);
}

__global__ __launch_bounds__(256) void packw_kernel(
    const float* __restrict__ Wq, const float* __restrict__ Wk, const float* __restrict__ Wv) {
    int i = blockIdx.x * 256 + threadIdx.x;      // over QKVN*EMBED
    int n = i >> 10;
    int k = i & 1023;
    int mat = n >> 10;
    int hn  = n & 1023;
    int h = hn >> 6, d = hn & 63;
    const float* w = (mat == 0) ? Wq : ((mat == 1) ? Wk : Wv);
    g_wqkvh[i] = __float2half_rn(w[((size_t)h * EMBED + k) * HEAD + d]);
}

__global__ __launch_bounds__(256) void wo2h_kernel(const float* __restrict__ Wo) {
    int i = (blockIdx.x * 256 + threadIdx.x) * 4;
    float4 v = *(const float4*)(Wo + i);
    *(__half2*)(g_woh + i)     = __floats2half2_rn(v.x, v.y);
    *(__half2*)(g_woh + i + 2) = __floats2half2_rn(v.z, v.w);
}

// ============================================================================
// fp16 GEMM body (R11, proven): C[128x128] = A[128xK] * B^T.
// ============================================================================
struct GemmAcc { float c[2][8][4]; };

__device__ __forceinline__ void gemm128h(
    GemmAcc& acc,
    const __half* __restrict__ aBase,
    const __half* __restrict__ bBase,
    int lda, int ldb)
{
    extern __shared__ __half sh[];
    __half (*As)[128][HPAD] = (__half(*)[128][HPAD])sh;
    __half (*Bs)[128][HPAD] = (__half(*)[128][HPAD])(sh + 2 * 128 * HPAD);

    const int tid  = threadIdx.x;
    const int lane = tid & 31;
    const int warp = tid >> 5;
    const int wm   = warp & 3;
    const int wn   = warp >> 2;
    const int fr   = lane & 15;
    const int fk   = (lane >> 4) * 8;

    int sr[4], scol[4];
    const __half* agp[4];
    const __half* bgp[4];
    #pragma unroll
    for (int j = 0; j < 4; j++) {
        int chunk = tid + j * 256;
        sr[j] = chunk >> 3; scol[j] = (chunk & 7) * 8;
        agp[j] = aBase + (size_t)sr[j] * lda + scol[j];
        bgp[j] = bBase + (size_t)sr[j] * ldb + scol[j];
    }

    #pragma unroll
    for (int j = 0; j < 4; j++) {
        cp16(&As[0][sr[j]][scol[j]], agp[j]);
        cp16(&Bs[0][sr[j]][scol[j]], bgp[j]);
    }
    CP_COMMIT();
    CP_WAIT0();
    __syncthreads();

    const int NK = EMBED / 64;
    for (int it = 0; it < NK; it++) {
        const int buf = it & 1;
        if (it + 1 < NK) {
            const int kc = (it + 1) * 64;
            #pragma unroll
            for (int j = 0; j < 4; j++) {
                cp16(&As[buf ^ 1][sr[j]][scol[j]], agp[j] + kc);
                cp16(&Bs[buf ^ 1][sr[j]][scol[j]], bgp[j] + kc);
            }
            CP_COMMIT();
        }

        #pragma unroll
        for (int ks = 0; ks < 4; ks++) {
            const int k0 = ks * 16 + fk;
            uint32_t a[2][4], b[4][4];
            #pragma unroll
            for (int mi = 0; mi < 2; mi++)
                ldsm4(a[mi], &As[buf][wm * 32 + mi * 16 + fr][k0]);
            #pragma unroll
            for (int np = 0; np < 4; np++)
                ldsm4(b[np], &Bs[buf][wn * 64 + np * 16 + fr][k0]);
            #pragma unroll
            for (int np = 0; np < 4; np++) {
                #pragma unroll
                for (int mi = 0; mi < 2; mi++) {
                    mma16(acc.c[mi][2 * np    ], a[mi][0], a[mi][1], a[mi][2], a[mi][3],
                          b[np][0], b[np][2]);
                    mma16(acc.c[mi][2 * np + 1], a[mi][0], a[mi][1], a[mi][2], a[mi][3],
                          b[np][1], b[np][3]);
                }
            }
        }

        if (it + 1 < NK) CP_WAIT0();
        __syncthreads();
    }
}

// ============================================================================
// Kernel 1: QKV GEMM (fp16) -> fp16 Q/K [B,H,S,D] (Q scaled), V [B,H,D,S].
// ============================================================================
__global__ __launch_bounds__(256, 2) void qkv_kernel()
{
    const int n0 = blockIdx.x * 128;
    const int m0 = blockIdx.y * 128;

    GemmAcc acc;
    #pragma unroll
    for (int mi = 0; mi < 2; mi++)
        #pragma unroll
        for (int ni = 0; ni < 8; ni++)
            #pragma unroll
            for (int e = 0; e < 4; e++) acc.c[mi][ni][e] = 0.0f;

    gemm128h(acc, g_xh + (size_t)m0 * EMBED, g_wqkvh + (size_t)n0 * EMBED,
             EMBED, EMBED);

    const int lane = threadIdx.x & 31;
    const int warp = threadIdx.x >> 5;
    const int g    = lane >> 2;
    const int t4   = lane & 3;
    const int wm   = warp & 3;
    const int wn   = warp >> 2;

    const int mat = n0 >> 10;
    const int b   = m0 >> 11;
    const int s0l = m0 & 2047;
    const int h   = ((n0 & 1023) >> 6) + wn;
    const size_t bhOff = (size_t)(b * NHEADS + h);

    if (mat < 2) {
        __half* dst = ((mat == 0) ? g_qh : g_kh) + bhOff * SEQ * HEAD;
        const float scale = (mat == 0) ? 0.125f : 1.0f;
        #pragma unroll
        for (int mi = 0; mi < 2; mi++) {
            int s0r = s0l + wm * 32 + mi * 16 + g;
            #pragma unroll
            for (int ni = 0; ni < 8; ni++) {
                int d = ni * 8 + t4 * 2;
                *(__half2*)(dst + (size_t)(s0r    ) * HEAD + d) =
                    __floats2half2_rn(acc.c[mi][ni][0] * scale, acc.c[mi][ni][1] * scale);
                *(__half2*)(dst + (size_t)(s0r + 8) * HEAD + d) =
                    __floats2half2_rn(acc.c[mi][ni][2] * scale, acc.c[mi][ni][3] * scale);
            }
        }
    } else {
        __half* dst = g_vh + bhOff * HEAD * SEQ;
        #pragma unroll
        for (int mi = 0; mi < 2; mi++) {
            int s0r = s0l + wm * 32 + mi * 16 + g;
            #pragma unroll
            for (int ni = 0; ni < 8; ni++) {
                int d = ni * 8 + t4 * 2;
                dst[(size_t)(d    ) * SEQ + s0r    ] = __float2half_rn(acc.c[mi][ni][0]);
                dst[(size_t)(d + 1) * SEQ + s0r    ] = __float2half_rn(acc.c[mi][ni][1]);
                dst[(size_t)(d    ) * SEQ + s0r + 8] = __float2half_rn(acc.c[mi][ni][2]);
                dst[(size_t)(d + 1) * SEQ + s0r + 8] = __float2half_rn(acc.c[mi][ni][3]);
            }
        }
    }
}

// ============================================================================
// Kernel 2: causal flash attention, fp16 mma, BN=64 keys/tile.
// BM=128 (8 warps x 16 rows), D=64.  3-stage cp.async K/V ring.  P in regs.
// ============================================================================
__global__ __launch_bounds__(256, 2) void attn_kernel()
{
    extern __shared__ __half sh[];
    __half (*Qs)[72]     = (__half(*)[72])sh;                             // 128 x 72
    __half (*Ks)[64][72] = (__half(*)[64][72])(sh + 128 * 72);            // 3 x 64 x 72
    __half (*Vs)[64][72] = (__half(*)[64][72])(sh + 128 * 72 + 3 * 64 * 72);

    const int bh = blockIdx.y;
    const int b  = bh >> 4;
    const int h  = bh & 15;
    const int qt = blockIdx.x;
    const int q0 = qt * 128;

    const int tid  = threadIdx.x;
    const int lane = tid & 31;
    const int warp = tid >> 5;
    const int g    = lane >> 2;
    const int t4   = lane & 3;
    const int fr   = lane & 15;
    const int fk   = (lane >> 4) * 8;

    const __half* qp = g_qh + ((size_t)bh * SEQ + q0) * HEAD;
    const __half* kp = g_kh + (size_t)bh * SEQ * HEAD;
    const __half* vp = g_vh + (size_t)bh * HEAD * SEQ;

    // ---- stage Q, build 4 a-frags ----
    {
        #pragma unroll
        for (int j = 0; j < 4; j++) {
            int chunk = tid + j * 256;
            int r = chunk >> 3, c = (chunk & 7) * 8;
            cp16(&Qs[r][c], qp + (size_t)r * HEAD + c);
        }
        CP_COMMIT();
        CP_WAIT0();
        __syncthreads();
    }
    uint32_t qa[4][4];
    #pragma unroll
    for (int kf = 0; kf < 4; kf++)
        ldsm4(qa[kf], &Qs[warp * 16 + fr][kf * 16 + fk]);

    float o[8][4];
    #pragma unroll
    for (int dn = 0; dn < 8; dn++)
        #pragma unroll
        for (int e = 0; e < 4; e++) o[dn][e] = 0.0f;

    float m0 = -1e30f, m1 = -1e30f, l0 = 0.0f, l1 = 0.0f;

    const int nkt   = (qt + 1) * 2;       // 64-key tiles covering [0, q0+128)
    const int row0b = q0 + warp * 16;
    const int qmaxw = row0b + 15;

    // K staging: 64x64 halves = 512 chunks -> 2/thread; same for V ([d][s])
    int kr[2], kc[2];
    #pragma unroll
    for (int j = 0; j < 2; j++) {
        int chunk = tid + j * 256;
        kr[j] = chunk >> 3; kc[j] = (chunk & 7) * 8;
    }

    #pragma unroll
    for (int st = 0; st < 2; st++) {
        const int k0 = st * 64;
        #pragma unroll
        for (int j = 0; j < 2; j++) {
            cp16(&Ks[st][kr[j]][kc[j]], kp + (size_t)(k0 + kr[j]) * HEAD + kc[j]);
            cp16(&Vs[st][kr[j]][kc[j]], vp + (size_t)kr[j] * SEQ + k0 + kc[j]);
        }
        CP_COMMIT();
    }

    int sc = 0;
    for (int kt = 0; kt < nkt; kt++) {
        const int k0 = kt * 64;

        CP_WAIT1();
        __syncthreads();

        if (kt + 2 < nkt) {
            int sp = sc + 2; if (sp >= 3) sp -= 3;
            const int kn = k0 + 128;
            #pragma unroll
            for (int j = 0; j < 2; j++) {
                cp16(&Ks[sp][kr[j]][kc[j]], kp + (size_t)(kn + kr[j]) * HEAD + kc[j]);
                cp16(&Vs[sp][kr[j]][kc[j]], vp + (size_t)kr[j] * SEQ + kn + kc[j]);
            }
            CP_COMMIT();
        }

        if (k0 <= qmaxw) {
            // ---- S = Q K^T : s[8][4] over 64 keys ----
            float s[8][4];
            #pragma unroll
            for (int nf = 0; nf < 8; nf++)
                #pragma unroll
                for (int e = 0; e < 4; e++) s[nf][e] = 0.0f;

            #pragma unroll
            for (int kf = 0; kf < 4; kf++) {
                #pragma unroll
                for (int np = 0; np < 4; np++) {
                    uint32_t bfr[4];
                    ldsm4(bfr, &Ks[sc][np * 16 + fr][kf * 16 + fk]);
                    mma16(s[2 * np    ], qa[kf][0], qa[kf][1], qa[kf][2], qa[kf][3],
                          bfr[0], bfr[2]);
                    mma16(s[2 * np + 1], qa[kf][0], qa[kf][1], qa[kf][2], qa[kf][3],
                          bfr[1], bfr[3]);
                }
            }

            // ---- causal mask ----
            const int r0 = row0b + g;
            const int r1 = r0 + 8;
            #pragma unroll
            for (int nf = 0; nf < 8; nf++) {
                int col0 = k0 + nf * 8 + t4 * 2;
                if (col0     > r0) s[nf][0] = -1e30f;
                if (col0 + 1 > r0) s[nf][1] = -1e30f;
                if (col0     > r1) s[nf][2] = -1e30f;
                if (col0 + 1 > r1) s[nf][3] = -1e30f;
            }

            // ---- online softmax ----
            float rm0 = -1e30f, rm1 = -1e30f;
            #pragma unroll
            for (int nf = 0; nf < 8; nf++) {
                rm0 = fmaxf(rm0, fmaxf(s[nf][0], s[nf][1]));
                rm1 = fmaxf(rm1, fmaxf(s[nf][2], s[nf][3]));
            }
            rm0 = fmaxf(rm0, __shfl_xor_sync(0xffffffffu, rm0, 1));
            rm0 = fmaxf(rm0, __shfl_xor_sync(0xffffffffu, rm0, 2));
            rm1 = fmaxf(rm1, __shfl_xor_sync(0xffffffffu, rm1, 1));
            rm1 = fmaxf(rm1, __shfl_xor_sync(0xffffffffu, rm1, 2));

            float nm0 = fmaxf(m0, rm0), nm1 = fmaxf(m1, rm1);
            float sc0 = __expf(m0 - nm0), sc1 = __expf(m1 - nm1);

            float sum0 = 0.0f, sum1 = 0.0f;
            #pragma unroll
            for (int nf = 0; nf < 8; nf++) {
                s[nf][0] = __expf(s[nf][0] - nm0);
                s[nf][1] = __expf(s[nf][1] - nm0);
                s[nf][2] = __expf(s[nf][2] - nm1);
                s[nf][3] = __expf(s[nf][3] - nm1);
                sum0 += s[nf][0] + s[nf][1];
                sum1 += s[nf][2] + s[nf][3];
            }
            sum0 += __shfl_xor_sync(0xffffffffu, sum0, 1);
            sum0 += __shfl_xor_sync(0xffffffffu, sum0, 2);
            sum1 += __shfl_xor_sync(0xffffffffu, sum1, 1);
            sum1 += __shfl_xor_sync(0xffffffffu, sum1, 2);

            l0 = l0 * sc0 + sum0;  m0 = nm0;
            l1 = l1 * sc1 + sum1;  m1 = nm1;

            #pragma unroll
            for (int dn = 0; dn < 8; dn++) {
                o[dn][0] *= sc0; o[dn][1] *= sc0;
                o[dn][2] *= sc1; o[dn][3] *= sc1;
            }

            // ---- O += P V : 4 kf (keys) x 4 np (d) ----
            #pragma unroll
            for (int kf = 0; kf < 4; kf++) {
                uint32_t pa0 = h2u(__floats2half2_rn(s[2 * kf    ][0], s[2 * kf    ][1]));
                uint32_t pa1 = h2u(__floats2half2_rn(s[2 * kf    ][2], s[2 * kf    ][3]));
                uint32_t pa2 = h2u(__floats2half2_rn(s[2 * kf + 1][0], s[2 * kf + 1][1]));
                uint32_t pa3 = h2u(__floats2half2_rn(s[2 * kf + 1][2], s[2 * kf + 1][3]));
                #pragma unroll
                for (int np = 0; np < 4; np++) {
                    uint32_t bfr[4];
                    ldsm4(bfr, &Vs[sc][np * 16 + fr][kf * 16 + fk]);
                    mma16(o[2 * np    ], pa0, pa1, pa2, pa3, bfr[0], bfr[2]);
                    mma16(o[2 * np + 1], pa0, pa1, pa2, pa3, bfr[1], bfr[3]);
                }
            }
        }

        if (++sc == 3) sc = 0;
    }

    // ---- epilogue ----
    const float inv0 = 1.0f / l0;
    const float inv1 = 1.0f / l1;
    const int r0 = q0 + warp * 16 + g;
    __half* ob = g_attnh + (size_t)b * SEQ * EMBED + (size_t)h * HEAD;
    #pragma unroll
    for (int dn = 0; dn < 8; dn++) {
        int d = dn * 8 + t4 * 2;
        *(__half2*)(ob + (size_t)(r0    ) * EMBED + d) =
            __floats2half2_rn(o[dn][0] * inv0, o[dn][1] * inv0);
        *(__half2*)(ob + (size_t)(r0 + 8) * EMBED + d) =
            __floats2half2_rn(o[dn][2] * inv1, o[dn][3] * inv1);
    }
}

// ============================================================================
// Kernel 3: output projection (fp16, proven).
// ============================================================================
__global__ __launch_bounds__(256, 2) void proj_kernel(
    const float* __restrict__ bo,
    float* __restrict__ out)
{
    const int e0 = blockIdx.x * 128;
    const int m0 = blockIdx.y * 128;

    GemmAcc acc;
    #pragma unroll
    for (int mi = 0; mi < 2; mi++)
        #pragma unroll
        for (int ni = 0; ni < 8; ni++)
            #pragma unroll
            for (int e = 0; e < 4; e++) acc.c[mi][ni][e] = 0.0f;

    gemm128h(acc, g_attnh + (size_t)m0 * EMBED, g_woh + (size_t)e0 * EMBED,
             EMBED, EMBED);

    const int lane = threadIdx.x & 31;
    const int warp = threadIdx.x >> 5;
    const int g    = lane >> 2;
    const int t4   = lane & 3;
    const int wm   = warp & 3;
    const int wn   = warp >> 2;

    #pragma unroll
    for (int mi = 0; mi < 2; mi++) {
        int r0 = m0 + wm * 32 + mi * 16 + g;
        #pragma unroll
        for (int ni = 0; ni < 8; ni++) {
            int e = e0 + wn * 64 + ni * 8 + t4 * 2;
            out[(size_t)(r0    ) * EMBED + e    ] = acc.c[mi][ni][0] + bo[e];
            out[(size_t)(r0    ) * EMBED + e + 1] = acc.c[mi][ni][1] + bo[e + 1];
            out[(size_t)(r0 + 8) * EMBED + e    ] = acc.c[mi][ni][2] + bo[e];
            out[(size_t)(r0 + 8) * EMBED + e + 1] = acc.c[mi][ni][3] + bo[e + 1];
        }
    }
}

// ============================================================================
extern "C" void kernel_launch(void* const* d_in, const int* in_sizes, int n_in,
                              void* d_out, int out_size)
{
    const float* x  = (const float*)d_in[0];
    const float* Wq = (const float*)d_in[1];
    const float* Wk = (const float*)d_in[2];
    const float* Wv = (const float*)d_in[3];
    const float* Wo = (const float*)d_in[4];
    const float* bo = (const float*)d_in[5];
    float* out = (float*)d_out;

    (void)in_sizes; (void)n_in; (void)out_size;

    cudaFuncSetAttribute(qkv_kernel,  cudaFuncAttributeMaxDynamicSharedMemorySize, GEMM_SMEM);
    cudaFuncSetAttribute(attn_kernel, cudaFuncAttributeMaxDynamicSharedMemorySize, ATTN_SMEM);
    cudaFuncSetAttribute(proj_kernel, cudaFuncAttributeMaxDynamicSharedMemorySize, GEMM_SMEM);

    x2h_kernel<<<NTOK * EMBED / 1024, 256>>>(x);
    packw_kernel<<<QKVN * EMBED / 256, 256>>>(Wq, Wk, Wv);
    wo2h_kernel<<<EMBED * EMBED / 1024, 256>>>(Wo);

    qkv_kernel<<<dim3(QKVN / 128, NTOK / 128), 256, GEMM_SMEM>>>();
    attn_kernel<<<dim3(SEQ / 128, BATCH * NHEADS), 256, ATTN_SMEM>>>();
    proj_kernel<<<dim3(EMBED / 128, NTOK / 128), 256, GEMM_SMEM>>>(bo, out);
}

// round 14
// speedup vs baseline: 1.5179x; 1.5179x over previous
#include <cuda_runtime.h>
#include <cuda_fp16.h>
#include <stdint.h>
#include <math.h>

#define BATCH  4
#define NHEADS 16
#define HEAD   64
#define SEQ    2048
#define EMBED  1024
#define QKVN   3072
#define NTOK   (BATCH * SEQ)   // 8192
#define HPAD   72              // half-row pad: 144B, ldmatrix phase conflict-free

// ---------------- scratch (device globals: allocation-free) ----------------
__device__ __half g_qh[BATCH * NHEADS * SEQ * HEAD];  // [B,H,S,D] fp16, pre-scaled
__device__ __half g_kh[BATCH * NHEADS * SEQ * HEAD];  // [B,H,S,D] fp16
__device__ __half g_vh[BATCH * NHEADS * HEAD * SEQ];  // [B,H,D,S] fp16 (transposed)
__device__ __half g_attnh[BATCH * SEQ * EMBED];       // [B,S,H*D] fp16
__device__ __half g_xh[NTOK * EMBED];                 // X fp16
__device__ __half g_wqkvh[QKVN * EMBED];              // packed [n][k] fp16
__device__ __half g_woh[EMBED * EMBED];               // Wo [e][f] fp16

// ---------------- helpers ----------------
__device__ __forceinline__ void mma16(float* c,
                                      uint32_t a0, uint32_t a1, uint32_t a2, uint32_t a3,
                                      uint32_t b0, uint32_t b1) {
    asm volatile(
        "mma.sync.aligned.m16n8k16.row.col.f32.f16.f16.f32 "
        "{%0,%1,%2,%3}, {%4,%5,%6,%7}, {%8,%9}, {%0,%1,%2,%3};"
        : "+f"(c[0]), "+f"(c[1]), "+f"(c[2]), "+f"(c[3])
        : "r"(a0), "r"(a1), "r"(a2), "r"(a3), "r"(b0), "r"(b1));
}

__device__ __forceinline__ void ldsm4(uint32_t* r, const void* p) {
    uint32_t a = (uint32_t)__cvta_generic_to_shared(p);
    asm volatile("ldmatrix.sync.aligned.m8n8.x4.shared.b16 {%0,%1,%2,%3}, [%4];"
                 : "=r"(r[0]), "=r"(r[1]), "=r"(r[2]), "=r"(r[3]) : "r"(a));
}

__device__ __forceinline__ void cp16(void* smem, const void* gmem) {
    uint32_t sa = (uint32_t)__cvta_generic_to_shared(smem);
    asm volatile("cp.async.cg.shared.global [%0], [%1], 16;" :: "r"(sa), "l"(gmem));
}
#define CP_COMMIT() asm volatile("cp.async.commit_group;")
#define CP_WAIT0()  asm volatile("cp.async.wait_group 0;")
#define CP_WAIT1()  asm volatile("cp.async.wait_group 1;")

__device__ __forceinline__ uint32_t h2u(__half2 h) { return *(uint32_t*)&h; }

// smem sizes (bytes)
#define GEMM_SMEM (2 * 2 * 128 * HPAD * 2)                           // 73728
#define ATTN_SMEM ((128 * 72 + 3 * 32 * 72 + 3 * 64 * 40) * 2)      // 47616

// ============================================================================
// Prep: single merged kernel (x->fp16, pack Wqkv, Wo->fp16).
// Block ranges: [0, 8192) x2h | [8192, 20480) packw | [20480, 21504) wo2h
// ============================================================================
__global__ __launch_bounds__(256) void prep_kernel(
    const float* __restrict__ x,
    const float* __restrict__ Wq, const float* __restrict__ Wk,
    const float* __restrict__ Wv, const float* __restrict__ Wo)
{
    const int blk = blockIdx.x;
    if (blk < NTOK) {   // x2h: 8192 blocks, 1024 floats each
        int i = (blk * 256 + threadIdx.x) * 4;
        float4 v = *(const float4*)(x + i);
        *(__half2*)(g_xh + i)     = __floats2half2_rn(v.x, v.y);
        *(__half2*)(g_xh + i + 2) = __floats2half2_rn(v.z, v.w);
    } else if (blk < NTOK + QKVN * EMBED / 256) {   // packw: 12288 blocks
        int i = (blk - NTOK) * 256 + threadIdx.x;
        int n = i >> 10;
        int k = i & 1023;
        int mat = n >> 10;
        int hn  = n & 1023;
        int h = hn >> 6, d = hn & 63;
        const float* w = (mat == 0) ? Wq : ((mat == 1) ? Wk : Wv);
        g_wqkvh[i] = __float2half_rn(w[((size_t)h * EMBED + k) * HEAD + d]);
    } else {   // wo2h: 1024 blocks
        int i = ((blk - NTOK - QKVN * EMBED / 256) * 256 + threadIdx.x) * 4;
        float4 v = *(const float4*)(Wo + i);
        *(__half2*)(g_woh + i)     = __floats2half2_rn(v.x, v.y);
        *(__half2*)(g_woh + i + 2) = __floats2half2_rn(v.z, v.w);
    }
}
#define PREP_BLOCKS (NTOK + QKVN * EMBED / 256 + EMBED * EMBED / 1024)

// ============================================================================
// fp16 GEMM body (R11, proven): C[128x128] = A[128xK] * B^T.
// K-chunk 64, 2-stage.  8 warps = 4(M) x 2(N), warp 32x64.
// ============================================================================
struct GemmAcc { float c[2][8][4]; };

__device__ __forceinline__ void gemm128h(
    GemmAcc& acc,
    const __half* __restrict__ aBase,
    const __half* __restrict__ bBase,
    int lda, int ldb)
{
    extern __shared__ __half sh[];
    __half (*As)[128][HPAD] = (__half(*)[128][HPAD])sh;
    __half (*Bs)[128][HPAD] = (__half(*)[128][HPAD])(sh + 2 * 128 * HPAD);

    const int tid  = threadIdx.x;
    const int lane = tid & 31;
    const int warp = tid >> 5;
    const int wm   = warp & 3;
    const int wn   = warp >> 2;
    const int fr   = lane & 15;
    const int fk   = (lane >> 4) * 8;

    int sr[4], scol[4];
    const __half* agp[4];
    const __half* bgp[4];
    #pragma unroll
    for (int j = 0; j < 4; j++) {
        int chunk = tid + j * 256;
        sr[j] = chunk >> 3; scol[j] = (chunk & 7) * 8;
        agp[j] = aBase + (size_t)sr[j] * lda + scol[j];
        bgp[j] = bBase + (size_t)sr[j] * ldb + scol[j];
    }

    #pragma unroll
    for (int j = 0; j < 4; j++) {
        cp16(&As[0][sr[j]][scol[j]], agp[j]);
        cp16(&Bs[0][sr[j]][scol[j]], bgp[j]);
    }
    CP_COMMIT();
    CP_WAIT0();
    __syncthreads();

    const int NK = EMBED / 64;
    for (int it = 0; it < NK; it++) {
        const int buf = it & 1;
        if (it + 1 < NK) {
            const int kc = (it + 1) * 64;
            #pragma unroll
            for (int j = 0; j < 4; j++) {
                cp16(&As[buf ^ 1][sr[j]][scol[j]], agp[j] + kc);
                cp16(&Bs[buf ^ 1][sr[j]][scol[j]], bgp[j] + kc);
            }
            CP_COMMIT();
        }

        #pragma unroll
        for (int ks = 0; ks < 4; ks++) {
            const int k0 = ks * 16 + fk;
            uint32_t a[2][4], b[4][4];
            #pragma unroll
            for (int mi = 0; mi < 2; mi++)
                ldsm4(a[mi], &As[buf][wm * 32 + mi * 16 + fr][k0]);
            #pragma unroll
            for (int np = 0; np < 4; np++)
                ldsm4(b[np], &Bs[buf][wn * 64 + np * 16 + fr][k0]);
            #pragma unroll
            for (int np = 0; np < 4; np++) {
                #pragma unroll
                for (int mi = 0; mi < 2; mi++) {
                    mma16(acc.c[mi][2 * np    ], a[mi][0], a[mi][1], a[mi][2], a[mi][3],
                          b[np][0], b[np][2]);
                    mma16(acc.c[mi][2 * np + 1], a[mi][0], a[mi][1], a[mi][2], a[mi][3],
                          b[np][1], b[np][3]);
                }
            }
        }

        if (it + 1 < NK) CP_WAIT0();
        __syncthreads();
    }
}

// ============================================================================
// Kernel 1: QKV GEMM (fp16) -> fp16 Q/K [B,H,S,D] (Q scaled), V [B,H,D,S].
// ============================================================================
__global__ __launch_bounds__(256, 2) void qkv_kernel()
{
    const int n0 = blockIdx.x * 128;
    const int m0 = blockIdx.y * 128;

    GemmAcc acc;
    #pragma unroll
    for (int mi = 0; mi < 2; mi++)
        #pragma unroll
        for (int ni = 0; ni < 8; ni++)
            #pragma unroll
            for (int e = 0; e < 4; e++) acc.c[mi][ni][e] = 0.0f;

    gemm128h(acc, g_xh + (size_t)m0 * EMBED, g_wqkvh + (size_t)n0 * EMBED,
             EMBED, EMBED);

    const int lane = threadIdx.x & 31;
    const int warp = threadIdx.x >> 5;
    const int g    = lane >> 2;
    const int t4   = lane & 3;
    const int wm   = warp & 3;
    const int wn   = warp >> 2;

    const int mat = n0 >> 10;
    const int b   = m0 >> 11;
    const int s0l = m0 & 2047;
    const int h   = ((n0 & 1023) >> 6) + wn;
    const size_t bhOff = (size_t)(b * NHEADS + h);

    if (mat < 2) {
        __half* dst = ((mat == 0) ? g_qh : g_kh) + bhOff * SEQ * HEAD;
        const float scale = (mat == 0) ? 0.125f : 1.0f;
        #pragma unroll
        for (int mi = 0; mi < 2; mi++) {
            int s0r = s0l + wm * 32 + mi * 16 + g;
            #pragma unroll
            for (int ni = 0; ni < 8; ni++) {
                int d = ni * 8 + t4 * 2;
                *(__half2*)(dst + (size_t)(s0r    ) * HEAD + d) =
                    __floats2half2_rn(acc.c[mi][ni][0] * scale, acc.c[mi][ni][1] * scale);
                *(__half2*)(dst + (size_t)(s0r + 8) * HEAD + d) =
                    __floats2half2_rn(acc.c[mi][ni][2] * scale, acc.c[mi][ni][3] * scale);
            }
        }
    } else {
        // V transposed: dst[d][s]
        __half* dst = g_vh + bhOff * HEAD * SEQ;
        #pragma unroll
        for (int mi = 0; mi < 2; mi++) {
            int s0r = s0l + wm * 32 + mi * 16 + g;
            #pragma unroll
            for (int ni = 0; ni < 8; ni++) {
                int d = ni * 8 + t4 * 2;
                dst[(size_t)(d    ) * SEQ + s0r    ] = __float2half_rn(acc.c[mi][ni][0]);
                dst[(size_t)(d + 1) * SEQ + s0r    ] = __float2half_rn(acc.c[mi][ni][1]);
                dst[(size_t)(d    ) * SEQ + s0r + 8] = __float2half_rn(acc.c[mi][ni][2]);
                dst[(size_t)(d + 1) * SEQ + s0r + 8] = __float2half_rn(acc.c[mi][ni][3]);
            }
        }
    }
}

// ============================================================================
// Kernel 2: causal flash attention, full fp16 mma (m16n8k16).  (R12, proven)
// BM=128 (8 warps x 16 rows), BN=32 keys, D=64.  3-stage cp.async K/V ring.
// P stays in registers.
// ============================================================================
__global__ __launch_bounds__(256, 2) void attn_kernel()
{
    extern __shared__ __half sh[];
    __half (*Qs)[72]     = (__half(*)[72])sh;                         // 128 x 72
    __half (*Ks)[32][72] = (__half(*)[32][72])(sh + 128 * 72);        // 3 x 32 x 72
    __half (*Vs)[64][40] = (__half(*)[64][40])(sh + 128 * 72 + 3 * 32 * 72); // 3 x 64 x 40

    const int bh = blockIdx.y;
    const int b  = bh >> 4;
    const int h  = bh & 15;
    const int qt = blockIdx.x;
    const int q0 = qt * 128;

    const int tid  = threadIdx.x;
    const int lane = tid & 31;
    const int warp = tid >> 5;
    const int g    = lane >> 2;
    const int t4   = lane & 3;
    const int fr   = lane & 15;
    const int fk   = (lane >> 4) * 8;

    const __half* qp = g_qh + ((size_t)bh * SEQ + q0) * HEAD;
    const __half* kp = g_kh + (size_t)bh * SEQ * HEAD;
    const __half* vp = g_vh + (size_t)bh * HEAD * SEQ;

    // ---- stage Q (fp16, pre-scaled), build 4 a-frags ----
    {
        #pragma unroll
        for (int j = 0; j < 4; j++) {
            int chunk = tid + j * 256;
            int r = chunk >> 3, c = (chunk & 7) * 8;
            cp16(&Qs[r][c], qp + (size_t)r * HEAD + c);
        }
        CP_COMMIT();
        CP_WAIT0();
        __syncthreads();
    }
    uint32_t qa[4][4];
    #pragma unroll
    for (int kf = 0; kf < 4; kf++)
        ldsm4(qa[kf], &Qs[warp * 16 + fr][kf * 16 + fk]);

    float o[8][4];
    #pragma unroll
    for (int dn = 0; dn < 8; dn++)
        #pragma unroll
        for (int e = 0; e < 4; e++) o[dn][e] = 0.0f;

    float m0 = -1e30f, m1 = -1e30f, l0 = 0.0f, l1 = 0.0f;

    const int nkt   = (qt + 1) * 4;
    const int row0b = q0 + warp * 16;
    const int qmaxw = row0b + 15;

    // K staging: 32 rows x 64 halves = 256 chunks (1/thread)
    const int kr = tid >> 3, kc = (tid & 7) * 8;
    // V staging: 64 rows(d) x 32 halves = 256 chunks (1/thread)
    const int vr = tid >> 2, vc = (tid & 3) * 8;

    #pragma unroll
    for (int st = 0; st < 2; st++) {
        const int k0 = st * 32;
        cp16(&Ks[st][kr][kc], kp + (size_t)(k0 + kr) * HEAD + kc);
        cp16(&Vs[st][vr][vc], vp + (size_t)vr * SEQ + k0 + vc);
        CP_COMMIT();
    }

    int sc = 0;
    for (int kt = 0; kt < nkt; kt++) {
        const int k0 = kt * 32;

        CP_WAIT1();
        __syncthreads();

        if (kt + 2 < nkt) {
            int sp = sc + 2; if (sp >= 3) sp -= 3;
            const int kn = k0 + 64;
            cp16(&Ks[sp][kr][kc], kp + (size_t)(kn + kr) * HEAD + kc);
            cp16(&Vs[sp][vr][vc], vp + (size_t)vr * SEQ + kn + vc);
            CP_COMMIT();
        }

        if (k0 <= qmaxw) {
            // ---- S = Q K^T ----
            float s[4][4];
            #pragma unroll
            for (int nf = 0; nf < 4; nf++)
                #pragma unroll
                for (int e = 0; e < 4; e++) s[nf][e] = 0.0f;

            #pragma unroll
            for (int kf = 0; kf < 4; kf++) {
                #pragma unroll
                for (int np = 0; np < 2; np++) {
                    uint32_t bfr[4];
                    ldsm4(bfr, &Ks[sc][np * 16 + fr][kf * 16 + fk]);
                    mma16(s[2 * np    ], qa[kf][0], qa[kf][1], qa[kf][2], qa[kf][3],
                          bfr[0], bfr[2]);
                    mma16(s[2 * np + 1], qa[kf][0], qa[kf][1], qa[kf][2], qa[kf][3],
                          bfr[1], bfr[3]);
                }
            }

            // ---- causal mask ----
            const int r0 = row0b + g;
            const int r1 = r0 + 8;
            #pragma unroll
            for (int nf = 0; nf < 4; nf++) {
                int col0 = k0 + nf * 8 + t4 * 2;
                if (col0     > r0) s[nf][0] = -1e30f;
                if (col0 + 1 > r0) s[nf][1] = -1e30f;
                if (col0     > r1) s[nf][2] = -1e30f;
                if (col0 + 1 > r1) s[nf][3] = -1e30f;
            }

            // ---- online softmax ----
            float rm0 = -1e30f, rm1 = -1e30f;
            #pragma unroll
            for (int nf = 0; nf < 4; nf++) {
                rm0 = fmaxf(rm0, fmaxf(s[nf][0], s[nf][1]));
                rm1 = fmaxf(rm1, fmaxf(s[nf][2], s[nf][3]));
            }
            rm0 = fmaxf(rm0, __shfl_xor_sync(0xffffffffu, rm0, 1));
            rm0 = fmaxf(rm0, __shfl_xor_sync(0xffffffffu, rm0, 2));
            rm1 = fmaxf(rm1, __shfl_xor_sync(0xffffffffu, rm1, 1));
            rm1 = fmaxf(rm1, __shfl_xor_sync(0xffffffffu, rm1, 2));

            float nm0 = fmaxf(m0, rm0), nm1 = fmaxf(m1, rm1);
            float sc0 = __expf(m0 - nm0), sc1 = __expf(m1 - nm1);

            float sum0 = 0.0f, sum1 = 0.0f;
            #pragma unroll
            for (int nf = 0; nf < 4; nf++) {
                s[nf][0] = __expf(s[nf][0] - nm0);
                s[nf][1] = __expf(s[nf][1] - nm0);
                s[nf][2] = __expf(s[nf][2] - nm1);
                s[nf][3] = __expf(s[nf][3] - nm1);
                sum0 += s[nf][0] + s[nf][1];
                sum1 += s[nf][2] + s[nf][3];
            }
            sum0 += __shfl_xor_sync(0xffffffffu, sum0, 1);
            sum0 += __shfl_xor_sync(0xffffffffu, sum0, 2);
            sum1 += __shfl_xor_sync(0xffffffffu, sum1, 1);
            sum1 += __shfl_xor_sync(0xffffffffu, sum1, 2);

            l0 = l0 * sc0 + sum0;  m0 = nm0;
            l1 = l1 * sc1 + sum1;  m1 = nm1;

            #pragma unroll
            for (int dn = 0; dn < 8; dn++) {
                o[dn][0] *= sc0; o[dn][1] *= sc0;
                o[dn][2] *= sc1; o[dn][3] *= sc1;
            }

            // ---- O += P V ----
            #pragma unroll
            for (int kf = 0; kf < 2; kf++) {
                uint32_t pa0 = h2u(__floats2half2_rn(s[2 * kf    ][0], s[2 * kf    ][1]));
                uint32_t pa1 = h2u(__floats2half2_rn(s[2 * kf    ][2], s[2 * kf    ][3]));
                uint32_t pa2 = h2u(__floats2half2_rn(s[2 * kf + 1][0], s[2 * kf + 1][1]));
                uint32_t pa3 = h2u(__floats2half2_rn(s[2 * kf + 1][2], s[2 * kf + 1][3]));
                #pragma unroll
                for (int np = 0; np < 4; np++) {
                    uint32_t bfr[4];
                    ldsm4(bfr, &Vs[sc][np * 16 + fr][kf * 16 + fk]);
                    mma16(o[2 * np    ], pa0, pa1, pa2, pa3, bfr[0], bfr[2]);
                    mma16(o[2 * np + 1], pa0, pa1, pa2, pa3, bfr[1], bfr[3]);
                }
            }
        }

        if (++sc == 3) sc = 0;
    }

    // ---- epilogue: normalize, write fp16 [B,S,H,D] ----
    const float inv0 = 1.0f / l0;
    const float inv1 = 1.0f / l1;
    const int r0 = q0 + warp * 16 + g;
    __half* ob = g_attnh + (size_t)b * SEQ * EMBED + (size_t)h * HEAD;
    #pragma unroll
    for (int dn = 0; dn < 8; dn++) {
        int d = dn * 8 + t4 * 2;
        *(__half2*)(ob + (size_t)(r0    ) * EMBED + d) =
            __floats2half2_rn(o[dn][0] * inv0, o[dn][1] * inv0);
        *(__half2*)(ob + (size_t)(r0 + 8) * EMBED + d) =
            __floats2half2_rn(o[dn][2] * inv1, o[dn][3] * inv1);
    }
}

// ============================================================================
// Kernel 3: output projection (fp16, proven).
// ============================================================================
__global__ __launch_bounds__(256, 2) void proj_kernel(
    const float* __restrict__ bo,
    float* __restrict__ out)
{
    const int e0 = blockIdx.x * 128;
    const int m0 = blockIdx.y * 128;

    GemmAcc acc;
    #pragma unroll
    for (int mi = 0; mi < 2; mi++)
        #pragma unroll
        for (int ni = 0; ni < 8; ni++)
            #pragma unroll
            for (int e = 0; e < 4; e++) acc.c[mi][ni][e] = 0.0f;

    gemm128h(acc, g_attnh + (size_t)m0 * EMBED, g_woh + (size_t)e0 * EMBED,
             EMBED, EMBED);

    const int lane = threadIdx.x & 31;
    const int warp = threadIdx.x >> 5;
    const int g    = lane >> 2;
    const int t4   = lane & 3;
    const int wm   = warp & 3;
    const int wn   = warp >> 2;

    #pragma unroll
    for (int mi = 0; mi < 2; mi++) {
        int r0 = m0 + wm * 32 + mi * 16 + g;
        #pragma unroll
        for (int ni = 0; ni < 8; ni++) {
            int e = e0 + wn * 64 + ni * 8 + t4 * 2;
            out[(size_t)(r0    ) * EMBED + e    ] = acc.c[mi][ni][0] + bo[e];
            out[(size_t)(r0    ) * EMBED + e + 1] = acc.c[mi][ni][1] + bo[e + 1];
            out[(size_t)(r0 + 8) * EMBED + e    ] = acc.c[mi][ni][2] + bo[e];
            out[(size_t)(r0 + 8) * EMBED + e + 1] = acc.c[mi][ni][3] + bo[e + 1];
        }
    }
}

// ============================================================================
extern "C" void kernel_launch(void* const* d_in, const int* in_sizes, int n_in,
                              void* d_out, int out_size)
{
    const float* x  = (const float*)d_in[0];
    const float* Wq = (const float*)d_in[1];
    const float* Wk = (const float*)d_in[2];
    const float* Wv = (const float*)d_in[3];
    const float* Wo = (const float*)d_in[4];
    const float* bo = (const float*)d_in[5];
    float* out = (float*)d_out;

    (void)in_sizes; (void)n_in; (void)out_size;

    cudaFuncSetAttribute(qkv_kernel,  cudaFuncAttributeMaxDynamicSharedMemorySize, GEMM_SMEM);
    cudaFuncSetAttribute(attn_kernel, cudaFuncAttributeMaxDynamicSharedMemorySize, ATTN_SMEM);
    cudaFuncSetAttribute(proj_kernel, cudaFuncAttributeMaxDynamicSharedMemorySize, GEMM_SMEM);

    prep_kernel<<<PREP_BLOCKS, 256>>>(x, Wq, Wk, Wv, Wo);

    qkv_kernel<<<dim3(QKVN / 128, NTOK / 128), 256, GEMM_SMEM>>>();
    attn_kernel<<<dim3(SEQ / 128, BATCH * NHEADS), 256, ATTN_SMEM>>>();
    proj_kernel<<<dim3(EMBED / 128, NTOK / 128), 256, GEMM_SMEM>>>(bo, out);
}

// round 15
// speedup vs baseline: 1.5571x; 1.0258x over previous
#include <cuda_runtime.h>
#include <cuda_fp16.h>
#include <stdint.h>
#include <math.h>

#define BATCH  4
#define NHEADS 16
#define HEAD   64
#define SEQ    2048
#define EMBED  1024
#define QKVN   3072
#define NTOK   (BATCH * SEQ)   // 8192
#define HPAD   72              // half-row pad: 144B, ldmatrix phase conflict-free
#define LOG2E  1.44269504088896340736f

// ---------------- scratch (device globals: allocation-free) ----------------
__device__ __half g_qh[BATCH * NHEADS * SEQ * HEAD];  // [B,H,S,D] fp16, scaled by log2e/8
__device__ __half g_kh[BATCH * NHEADS * SEQ * HEAD];  // [B,H,S,D] fp16
__device__ __half g_vh[BATCH * NHEADS * HEAD * SEQ];  // [B,H,D,S] fp16 (transposed)
__device__ __half g_attnh[BATCH * SEQ * EMBED];       // [B,S,H*D] fp16
__device__ __half g_xh[NTOK * EMBED];                 // X fp16
__device__ __half g_wqkvh[QKVN * EMBED];              // packed [n][k] fp16
__device__ __half g_woh[EMBED * EMBED];               // Wo [e][f] fp16

// ---------------- helpers ----------------
__device__ __forceinline__ void mma16(float* c,
                                      uint32_t a0, uint32_t a1, uint32_t a2, uint32_t a3,
                                      uint32_t b0, uint32_t b1) {
    asm volatile(
        "mma.sync.aligned.m16n8k16.row.col.f32.f16.f16.f32 "
        "{%0,%1,%2,%3}, {%4,%5,%6,%7}, {%8,%9}, {%0,%1,%2,%3};"
        : "+f"(c[0]), "+f"(c[1]), "+f"(c[2]), "+f"(c[3])
        : "r"(a0), "r"(a1), "r"(a2), "r"(a3), "r"(b0), "r"(b1));
}

__device__ __forceinline__ void ldsm4(uint32_t* r, const void* p) {
    uint32_t a = (uint32_t)__cvta_generic_to_shared(p);
    asm volatile("ldmatrix.sync.aligned.m8n8.x4.shared.b16 {%0,%1,%2,%3}, [%4];"
                 : "=r"(r[0]), "=r"(r[1]), "=r"(r[2]), "=r"(r[3]) : "r"(a));
}

__device__ __forceinline__ void cp16(void* smem, const void* gmem) {
    uint32_t sa = (uint32_t)__cvta_generic_to_shared(smem);
    asm volatile("cp.async.cg.shared.global [%0], [%1], 16;" :: "r"(sa), "l"(gmem));
}
#define CP_COMMIT() asm volatile("cp.async.commit_group;")
#define CP_WAIT0()  asm volatile("cp.async.wait_group 0;")
#define CP_WAIT1()  asm volatile("cp.async.wait_group 1;")

__device__ __forceinline__ uint32_t h2u(__half2 h) { return *(uint32_t*)&h; }

// smem sizes (bytes)
#define GEMM_SMEM (2 * 2 * 128 * HPAD * 2)                           // 73728
#define ATTN_SMEM ((128 * 72 + 3 * 32 * 72 + 3 * 64 * 40) * 2)      // 47616

// ============================================================================
// Prep: single merged kernel (x->fp16, pack Wqkv, Wo->fp16).
// ============================================================================
__global__ __launch_bounds__(256) void prep_kernel(
    const float* __restrict__ x,
    const float* __restrict__ Wq, const float* __restrict__ Wk,
    const float* __restrict__ Wv, const float* __restrict__ Wo)
{
    const int blk = blockIdx.x;
    if (blk < NTOK) {   // x2h: 8192 blocks
        int i = (blk * 256 + threadIdx.x) * 4;
        float4 v = *(const float4*)(x + i);
        *(__half2*)(g_xh + i)     = __floats2half2_rn(v.x, v.y);
        *(__half2*)(g_xh + i + 2) = __floats2half2_rn(v.z, v.w);
    } else if (blk < NTOK + QKVN * EMBED / 256) {   // packw: 12288 blocks
        int i = (blk - NTOK) * 256 + threadIdx.x;
        int n = i >> 10;
        int k = i & 1023;
        int mat = n >> 10;
        int hn  = n & 1023;
        int h = hn >> 6, d = hn & 63;
        const float* w = (mat == 0) ? Wq : ((mat == 1) ? Wk : Wv);
        g_wqkvh[i] = __float2half_rn(w[((size_t)h * EMBED + k) * HEAD + d]);
    } else {   // wo2h: 1024 blocks
        int i = ((blk - NTOK - QKVN * EMBED / 256) * 256 + threadIdx.x) * 4;
        float4 v = *(const float4*)(Wo + i);
        *(__half2*)(g_woh + i)     = __floats2half2_rn(v.x, v.y);
        *(__half2*)(g_woh + i + 2) = __floats2half2_rn(v.z, v.w);
    }
}
#define PREP_BLOCKS (NTOK + QKVN * EMBED / 256 + EMBED * EMBED / 1024)

// ============================================================================
// fp16 GEMM body (proven): C[128x128] = A[128xK] * B^T.
// ============================================================================
struct GemmAcc { float c[2][8][4]; };

__device__ __forceinline__ void gemm128h(
    GemmAcc& acc,
    const __half* __restrict__ aBase,
    const __half* __restrict__ bBase,
    int lda, int ldb)
{
    extern __shared__ __half sh[];
    __half (*As)[128][HPAD] = (__half(*)[128][HPAD])sh;
    __half (*Bs)[128][HPAD] = (__half(*)[128][HPAD])(sh + 2 * 128 * HPAD);

    const int tid  = threadIdx.x;
    const int lane = tid & 31;
    const int warp = tid >> 5;
    const int wm   = warp & 3;
    const int wn   = warp >> 2;
    const int fr   = lane & 15;
    const int fk   = (lane >> 4) * 8;

    int sr[4], scol[4];
    const __half* agp[4];
    const __half* bgp[4];
    #pragma unroll
    for (int j = 0; j < 4; j++) {
        int chunk = tid + j * 256;
        sr[j] = chunk >> 3; scol[j] = (chunk & 7) * 8;
        agp[j] = aBase + (size_t)sr[j] * lda + scol[j];
        bgp[j] = bBase + (size_t)sr[j] * ldb + scol[j];
    }

    #pragma unroll
    for (int j = 0; j < 4; j++) {
        cp16(&As[0][sr[j]][scol[j]], agp[j]);
        cp16(&Bs[0][sr[j]][scol[j]], bgp[j]);
    }
    CP_COMMIT();
    CP_WAIT0();
    __syncthreads();

    const int NK = EMBED / 64;
    for (int it = 0; it < NK; it++) {
        const int buf = it & 1;
        if (it + 1 < NK) {
            const int kc = (it + 1) * 64;
            #pragma unroll
            for (int j = 0; j < 4; j++) {
                cp16(&As[buf ^ 1][sr[j]][scol[j]], agp[j] + kc);
                cp16(&Bs[buf ^ 1][sr[j]][scol[j]], bgp[j] + kc);
            }
            CP_COMMIT();
        }

        #pragma unroll
        for (int ks = 0; ks < 4; ks++) {
            const int k0 = ks * 16 + fk;
            uint32_t a[2][4], b[4][4];
            #pragma unroll
            for (int mi = 0; mi < 2; mi++)
                ldsm4(a[mi], &As[buf][wm * 32 + mi * 16 + fr][k0]);
            #pragma unroll
            for (int np = 0; np < 4; np++)
                ldsm4(b[np], &Bs[buf][wn * 64 + np * 16 + fr][k0]);
            #pragma unroll
            for (int np = 0; np < 4; np++) {
                #pragma unroll
                for (int mi = 0; mi < 2; mi++) {
                    mma16(acc.c[mi][2 * np    ], a[mi][0], a[mi][1], a[mi][2], a[mi][3],
                          b[np][0], b[np][2]);
                    mma16(acc.c[mi][2 * np + 1], a[mi][0], a[mi][1], a[mi][2], a[mi][3],
                          b[np][1], b[np][3]);
                }
            }
        }

        if (it + 1 < NK) CP_WAIT0();
        __syncthreads();
    }
}

// ============================================================================
// Kernel 1: QKV GEMM (fp16) -> fp16 Q/K [B,H,S,D] (Q scaled by log2e/8),
// V [B,H,D,S].
// ============================================================================
__global__ __launch_bounds__(256, 2) void qkv_kernel()
{
    const int n0 = blockIdx.x * 128;
    const int m0 = blockIdx.y * 128;

    GemmAcc acc;
    #pragma unroll
    for (int mi = 0; mi < 2; mi++)
        #pragma unroll
        for (int ni = 0; ni < 8; ni++)
            #pragma unroll
            for (int e = 0; e < 4; e++) acc.c[mi][ni][e] = 0.0f;

    gemm128h(acc, g_xh + (size_t)m0 * EMBED, g_wqkvh + (size_t)n0 * EMBED,
             EMBED, EMBED);

    const int lane = threadIdx.x & 31;
    const int warp = threadIdx.x >> 5;
    const int g    = lane >> 2;
    const int t4   = lane & 3;
    const int wm   = warp & 3;
    const int wn   = warp >> 2;

    const int mat = n0 >> 10;
    const int b   = m0 >> 11;
    const int s0l = m0 & 2047;
    const int h   = ((n0 & 1023) >> 6) + wn;
    const size_t bhOff = (size_t)(b * NHEADS + h);

    if (mat < 2) {
        __half* dst = ((mat == 0) ? g_qh : g_kh) + bhOff * SEQ * HEAD;
        const float scale = (mat == 0) ? (0.125f * LOG2E) : 1.0f;   // log2e absorbed into Q
        #pragma unroll
        for (int mi = 0; mi < 2; mi++) {
            int s0r = s0l + wm * 32 + mi * 16 + g;
            #pragma unroll
            for (int ni = 0; ni < 8; ni++) {
                int d = ni * 8 + t4 * 2;
                *(__half2*)(dst + (size_t)(s0r    ) * HEAD + d) =
                    __floats2half2_rn(acc.c[mi][ni][0] * scale, acc.c[mi][ni][1] * scale);
                *(__half2*)(dst + (size_t)(s0r + 8) * HEAD + d) =
                    __floats2half2_rn(acc.c[mi][ni][2] * scale, acc.c[mi][ni][3] * scale);
            }
        }
    } else {
        __half* dst = g_vh + bhOff * HEAD * SEQ;
        #pragma unroll
        for (int mi = 0; mi < 2; mi++) {
            int s0r = s0l + wm * 32 + mi * 16 + g;
            #pragma unroll
            for (int ni = 0; ni < 8; ni++) {
                int d = ni * 8 + t4 * 2;
                dst[(size_t)(d    ) * SEQ + s0r    ] = __float2half_rn(acc.c[mi][ni][0]);
                dst[(size_t)(d + 1) * SEQ + s0r    ] = __float2half_rn(acc.c[mi][ni][1]);
                dst[(size_t)(d    ) * SEQ + s0r + 8] = __float2half_rn(acc.c[mi][ni][2]);
                dst[(size_t)(d + 1) * SEQ + s0r + 8] = __float2half_rn(acc.c[mi][ni][3]);
            }
        }
    }
}

// ============================================================================
// Kernel 2: causal flash attention, fp16 mma, exp2-domain softmax.
// BM=128 (8 warps x 16 rows), BN=32 keys, D=64.  3-stage cp.async K/V ring.
// ============================================================================
__global__ __launch_bounds__(256, 2) void attn_kernel()
{
    extern __shared__ __half sh[];
    __half (*Qs)[72]     = (__half(*)[72])sh;                         // 128 x 72
    __half (*Ks)[32][72] = (__half(*)[32][72])(sh + 128 * 72);        // 3 x 32 x 72
    __half (*Vs)[64][40] = (__half(*)[64][40])(sh + 128 * 72 + 3 * 32 * 72); // 3 x 64 x 40

    const int bh = blockIdx.y;
    const int b  = bh >> 4;
    const int h  = bh & 15;
    const int qt = blockIdx.x;
    const int q0 = qt * 128;

    const int tid  = threadIdx.x;
    const int lane = tid & 31;
    const int warp = tid >> 5;
    const int g    = lane >> 2;
    const int t4   = lane & 3;
    const int fr   = lane & 15;
    const int fk   = (lane >> 4) * 8;

    const __half* qp = g_qh + ((size_t)bh * SEQ + q0) * HEAD;
    const __half* kp = g_kh + (size_t)bh * SEQ * HEAD;
    const __half* vp = g_vh + (size_t)bh * HEAD * SEQ;

    // ---- stage Q, build 4 a-frags ----
    {
        #pragma unroll
        for (int j = 0; j < 4; j++) {
            int chunk = tid + j * 256;
            int r = chunk >> 3, c = (chunk & 7) * 8;
            cp16(&Qs[r][c], qp + (size_t)r * HEAD + c);
        }
        CP_COMMIT();
        CP_WAIT0();
        __syncthreads();
    }
    uint32_t qa[4][4];
    #pragma unroll
    for (int kf = 0; kf < 4; kf++)
        ldsm4(qa[kf], &Qs[warp * 16 + fr][kf * 16 + fk]);

    float o[8][4];
    #pragma unroll
    for (int dn = 0; dn < 8; dn++)
        #pragma unroll
        for (int e = 0; e < 4; e++) o[dn][e] = 0.0f;

    float m0 = -1e30f, m1 = -1e30f, l0 = 0.0f, l1 = 0.0f;

    const int nkt   = (qt + 1) * 4;
    const int row0b = q0 + warp * 16;
    const int qmaxw = row0b + 15;

    const int kr = tid >> 3, kc = (tid & 7) * 8;
    const int vr = tid >> 2, vc = (tid & 3) * 8;

    #pragma unroll
    for (int st = 0; st < 2; st++) {
        const int k0 = st * 32;
        cp16(&Ks[st][kr][kc], kp + (size_t)(k0 + kr) * HEAD + kc);
        cp16(&Vs[st][vr][vc], vp + (size_t)vr * SEQ + k0 + vc);
        CP_COMMIT();
    }

    int sc = 0;
    for (int kt = 0; kt < nkt; kt++) {
        const int k0 = kt * 32;

        CP_WAIT1();
        __syncthreads();

        if (kt + 2 < nkt) {
            int sp = sc + 2; if (sp >= 3) sp -= 3;
            const int kn = k0 + 64;
            cp16(&Ks[sp][kr][kc], kp + (size_t)(kn + kr) * HEAD + kc);
            cp16(&Vs[sp][vr][vc], vp + (size_t)vr * SEQ + kn + vc);
            CP_COMMIT();
        }

        if (k0 <= qmaxw) {
            // ---- S = Q K^T (log2-domain scores) ----
            float s[4][4];
            #pragma unroll
            for (int nf = 0; nf < 4; nf++)
                #pragma unroll
                for (int e = 0; e < 4; e++) s[nf][e] = 0.0f;

            #pragma unroll
            for (int kf = 0; kf < 4; kf++) {
                #pragma unroll
                for (int np = 0; np < 2; np++) {
                    uint32_t bfr[4];
                    ldsm4(bfr, &Ks[sc][np * 16 + fr][kf * 16 + fk]);
                    mma16(s[2 * np    ], qa[kf][0], qa[kf][1], qa[kf][2], qa[kf][3],
                          bfr[0], bfr[2]);
                    mma16(s[2 * np + 1], qa[kf][0], qa[kf][1], qa[kf][2], qa[kf][3],
                          bfr[1], bfr[3]);
                }
            }

            // ---- causal mask (skipped on fully-unmasked tiles) ----
            const int r0 = row0b + g;
            const int r1 = r0 + 8;
            if (k0 + 31 > row0b) {
                #pragma unroll
                for (int nf = 0; nf < 4; nf++) {
                    int col0 = k0 + nf * 8 + t4 * 2;
                    if (col0     > r0) s[nf][0] = -1e30f;
                    if (col0 + 1 > r0) s[nf][1] = -1e30f;
                    if (col0     > r1) s[nf][2] = -1e30f;
                    if (col0 + 1 > r1) s[nf][3] = -1e30f;
                }
            }

            // ---- online softmax (exp2 domain) ----
            float rm0 = -1e30f, rm1 = -1e30f;
            #pragma unroll
            for (int nf = 0; nf < 4; nf++) {
                rm0 = fmaxf(rm0, fmaxf(s[nf][0], s[nf][1]));
                rm1 = fmaxf(rm1, fmaxf(s[nf][2], s[nf][3]));
            }
            rm0 = fmaxf(rm0, __shfl_xor_sync(0xffffffffu, rm0, 1));
            rm0 = fmaxf(rm0, __shfl_xor_sync(0xffffffffu, rm0, 2));
            rm1 = fmaxf(rm1, __shfl_xor_sync(0xffffffffu, rm1, 1));
            rm1 = fmaxf(rm1, __shfl_xor_sync(0xffffffffu, rm1, 2));

            float nm0 = fmaxf(m0, rm0), nm1 = fmaxf(m1, rm1);
            float sc0 = exp2f(m0 - nm0), sc1 = exp2f(m1 - nm1);

            float sum0 = 0.0f, sum1 = 0.0f;
            #pragma unroll
            for (int nf = 0; nf < 4; nf++) {
                s[nf][0] = exp2f(s[nf][0] - nm0);
                s[nf][1] = exp2f(s[nf][1] - nm0);
                s[nf][2] = exp2f(s[nf][2] - nm1);
                s[nf][3] = exp2f(s[nf][3] - nm1);
                sum0 += s[nf][0] + s[nf][1];
                sum1 += s[nf][2] + s[nf][3];
            }
            sum0 += __shfl_xor_sync(0xffffffffu, sum0, 1);
            sum0 += __shfl_xor_sync(0xffffffffu, sum0, 2);
            sum1 += __shfl_xor_sync(0xffffffffu, sum1, 1);
            sum1 += __shfl_xor_sync(0xffffffffu, sum1, 2);

            l0 = l0 * sc0 + sum0;  m0 = nm0;
            l1 = l1 * sc1 + sum1;  m1 = nm1;

            #pragma unroll
            for (int dn = 0; dn < 8; dn++) {
                o[dn][0] *= sc0; o[dn][1] *= sc0;
                o[dn][2] *= sc1; o[dn][3] *= sc1;
            }

            // ---- O += P V ----
            #pragma unroll
            for (int kf = 0; kf < 2; kf++) {
                uint32_t pa0 = h2u(__floats2half2_rn(s[2 * kf    ][0], s[2 * kf    ][1]));
                uint32_t pa1 = h2u(__floats2half2_rn(s[2 * kf    ][2], s[2 * kf    ][3]));
                uint32_t pa2 = h2u(__floats2half2_rn(s[2 * kf + 1][0], s[2 * kf + 1][1]));
                uint32_t pa3 = h2u(__floats2half2_rn(s[2 * kf + 1][2], s[2 * kf + 1][3]));
                #pragma unroll
                for (int np = 0; np < 4; np++) {
                    uint32_t bfr[4];
                    ldsm4(bfr, &Vs[sc][np * 16 + fr][kf * 16 + fk]);
                    mma16(o[2 * np    ], pa0, pa1, pa2, pa3, bfr[0], bfr[2]);
                    mma16(o[2 * np + 1], pa0, pa1, pa2, pa3, bfr[1], bfr[3]);
                }
            }
        }

        if (++sc == 3) sc = 0;
    }

    // ---- epilogue: normalize, write fp16 [B,S,H,D] ----
    const float inv0 = 1.0f / l0;
    const float inv1 = 1.0f / l1;
    const int r0 = q0 + warp * 16 + g;
    __half* ob = g_attnh + (size_t)b * SEQ * EMBED + (size_t)h * HEAD;
    #pragma unroll
    for (int dn = 0; dn < 8; dn++) {
        int d = dn * 8 + t4 * 2;
        *(__half2*)(ob + (size_t)(r0    ) * EMBED + d) =
            __floats2half2_rn(o[dn][0] * inv0, o[dn][1] * inv0);
        *(__half2*)(ob + (size_t)(r0 + 8) * EMBED + d) =
            __floats2half2_rn(o[dn][2] * inv1, o[dn][3] * inv1);
    }
}

// ============================================================================
// Kernel 3: output projection (fp16, proven).
// ============================================================================
__global__ __launch_bounds__(256, 2) void proj_kernel(
    const float* __restrict__ bo,
    float* __restrict__ out)
{
    const int e0 = blockIdx.x * 128;
    const int m0 = blockIdx.y * 128;

    GemmAcc acc;
    #pragma unroll
    for (int mi = 0; mi < 2; mi++)
        #pragma unroll
        for (int ni = 0; ni < 8; ni++)
            #pragma unroll
            for (int e = 0; e < 4; e++) acc.c[mi][ni][e] = 0.0f;

    gemm128h(acc, g_attnh + (size_t)m0 * EMBED, g_woh + (size_t)e0 * EMBED,
             EMBED, EMBED);

    const int lane = threadIdx.x & 31;
    const int warp = threadIdx.x >> 5;
    const int g    = lane >> 2;
    const int t4   = lane & 3;
    const int wm   = warp & 3;
    const int wn   = warp >> 2;

    #pragma unroll
    for (int mi = 0; mi < 2; mi++) {
        int r0 = m0 + wm * 32 + mi * 16 + g;
        #pragma unroll
        for (int ni = 0; ni < 8; ni++) {
            int e = e0 + wn * 64 + ni * 8 + t4 * 2;
            out[(size_t)(r0    ) * EMBED + e    ] = acc.c[mi][ni][0] + bo[e];
            out[(size_t)(r0    ) * EMBED + e + 1] = acc.c[mi][ni][1] + bo[e + 1];
            out[(size_t)(r0 + 8) * EMBED + e    ] = acc.c[mi][ni][2] + bo[e];
            out[(size_t)(r0 + 8) * EMBED + e + 1] = acc.c[mi][ni][3] + bo[e + 1];
        }
    }
}

// ============================================================================
extern "C" void kernel_launch(void* const* d_in, const int* in_sizes, int n_in,
                              void* d_out, int out_size)
{
    const float* x  = (const float*)d_in[0];
    const float* Wq = (const float*)d_in[1];
    const float* Wk = (const float*)d_in[2];
    const float* Wv = (const float*)d_in[3];
    const float* Wo = (const float*)d_in[4];
    const float* bo = (const float*)d_in[5];
    float* out = (float*)d_out;

    (void)in_sizes; (void)n_in; (void)out_size;

    cudaFuncSetAttribute(qkv_kernel,  cudaFuncAttributeMaxDynamicSharedMemorySize, GEMM_SMEM);
    cudaFuncSetAttribute(attn_kernel, cudaFuncAttributeMaxDynamicSharedMemorySize, ATTN_SMEM);
    cudaFuncSetAttribute(proj_kernel, cudaFuncAttributeMaxDynamicSharedMemorySize, GEMM_SMEM);

    prep_kernel<<<PREP_BLOCKS, 256>>>(x, Wq, Wk, Wv, Wo);

    qkv_kernel<<<dim3(QKVN / 128, NTOK / 128), 256, GEMM_SMEM>>>();
    attn_kernel<<<dim3(SEQ / 128, BATCH * NHEADS), 256, ATTN_SMEM>>>();
    proj_kernel<<<dim3(EMBED / 128, NTOK / 128), 256, GEMM_SMEM>>>(bo, out);
}

// round 16
// speedup vs baseline: 1.5653x; 1.0053x over previous
#include <cuda_runtime.h>
#include <cuda_fp16.h>
#include <stdint.h>
#include <math.h>

#define BATCH  4
#define NHEADS 16
#define HEAD   64
#define SEQ    2048
#define EMBED  1024
#define QKVN   3072
#define NTOK   (BATCH * SEQ)   // 8192
#define HPAD   72              // half-row pad: 144B, ldmatrix phase conflict-free
#define LOG2E  1.44269504088896340736f

// ---------------- scratch (device globals: allocation-free) ----------------
__device__ __half g_qh[BATCH * NHEADS * SEQ * HEAD];  // [B,H,S,D] fp16, scaled by log2e/8
__device__ __half g_kh[BATCH * NHEADS * SEQ * HEAD];  // [B,H,S,D] fp16
__device__ __half g_vh[BATCH * NHEADS * HEAD * SEQ];  // [B,H,D,S] fp16 (transposed)
__device__ __half g_attnh[BATCH * SEQ * EMBED];       // [B,S,H*D] fp16
__device__ __half g_xh[NTOK * EMBED];                 // X fp16
__device__ __half g_wqkvh[QKVN * EMBED];              // packed [n][k] fp16
__device__ __half g_woh[EMBED * EMBED];               // Wo [e][f] fp16

// ---------------- helpers ----------------
__device__ __forceinline__ void mma16(float* c,
                                      uint32_t a0, uint32_t a1, uint32_t a2, uint32_t a3,
                                      uint32_t b0, uint32_t b1) {
    asm volatile(
        "mma.sync.aligned.m16n8k16.row.col.f32.f16.f16.f32 "
        "{%0,%1,%2,%3}, {%4,%5,%6,%7}, {%8,%9}, {%0,%1,%2,%3};"
        : "+f"(c[0]), "+f"(c[1]), "+f"(c[2]), "+f"(c[3])
        : "r"(a0), "r"(a1), "r"(a2), "r"(a3), "r"(b0), "r"(b1));
}

__device__ __forceinline__ void ldsm4(uint32_t* r, const void* p) {
    uint32_t a = (uint32_t)__cvta_generic_to_shared(p);
    asm volatile("ldmatrix.sync.aligned.m8n8.x4.shared.b16 {%0,%1,%2,%3}, [%4];"
                 : "=r"(r[0]), "=r"(r[1]), "=r"(r[2]), "=r"(r[3]) : "r"(a));
}

__device__ __forceinline__ void cp16(void* smem, const void* gmem) {
    uint32_t sa = (uint32_t)__cvta_generic_to_shared(smem);
    asm volatile("cp.async.cg.shared.global [%0], [%1], 16;" :: "r"(sa), "l"(gmem));
}
#define CP_COMMIT() asm volatile("cp.async.commit_group;")
#define CP_WAIT0()  asm volatile("cp.async.wait_group 0;")
#define CP_WAIT1()  asm volatile("cp.async.wait_group 1;")

__device__ __forceinline__ uint32_t h2u(__half2 h) { return *(uint32_t*)&h; }

// smem sizes (bytes)
#define GEMM_SMEM (2 * 2 * 128 * HPAD * 2)                           // 73728
#define ATTN_SMEM ((128 * 72 + 3 * 32 * 72 + 3 * 64 * 40) * 2)      // 47616

// ============================================================================
// Prep: single merged kernel (x->fp16, pack Wqkv, Wo->fp16).
// ============================================================================
__global__ __launch_bounds__(256) void prep_kernel(
    const float* __restrict__ x,
    const float* __restrict__ Wq, const float* __restrict__ Wk,
    const float* __restrict__ Wv, const float* __restrict__ Wo)
{
    const int blk = blockIdx.x;
    if (blk < NTOK) {   // x2h: 8192 blocks
        int i = (blk * 256 + threadIdx.x) * 4;
        float4 v = *(const float4*)(x + i);
        *(__half2*)(g_xh + i)     = __floats2half2_rn(v.x, v.y);
        *(__half2*)(g_xh + i + 2) = __floats2half2_rn(v.z, v.w);
    } else if (blk < NTOK + QKVN * EMBED / 256) {   // packw: 12288 blocks
        int i = (blk - NTOK) * 256 + threadIdx.x;
        int n = i >> 10;
        int k = i & 1023;
        int mat = n >> 10;
        int hn  = n & 1023;
        int h = hn >> 6, d = hn & 63;
        const float* w = (mat == 0) ? Wq : ((mat == 1) ? Wk : Wv);
        g_wqkvh[i] = __float2half_rn(w[((size_t)h * EMBED + k) * HEAD + d]);
    } else {   // wo2h: 1024 blocks
        int i = ((blk - NTOK - QKVN * EMBED / 256) * 256 + threadIdx.x) * 4;
        float4 v = *(const float4*)(Wo + i);
        *(__half2*)(g_woh + i)     = __floats2half2_rn(v.x, v.y);
        *(__half2*)(g_woh + i + 2) = __floats2half2_rn(v.z, v.w);
    }
}
#define PREP_BLOCKS (NTOK + QKVN * EMBED / 256 + EMBED * EMBED / 1024)

// ============================================================================
// fp16 GEMM body (proven): C[128x128] = A[128xK] * B^T.
// ============================================================================
struct GemmAcc { float c[2][8][4]; };

__device__ __forceinline__ void gemm128h(
    GemmAcc& acc,
    const __half* __restrict__ aBase,
    const __half* __restrict__ bBase,
    int lda, int ldb)
{
    extern __shared__ __half sh[];
    __half (*As)[128][HPAD] = (__half(*)[128][HPAD])sh;
    __half (*Bs)[128][HPAD] = (__half(*)[128][HPAD])(sh + 2 * 128 * HPAD);

    const int tid  = threadIdx.x;
    const int lane = tid & 31;
    const int warp = tid >> 5;
    const int wm   = warp & 3;
    const int wn   = warp >> 2;
    const int fr   = lane & 15;
    const int fk   = (lane >> 4) * 8;

    int sr[4], scol[4];
    const __half* agp[4];
    const __half* bgp[4];
    #pragma unroll
    for (int j = 0; j < 4; j++) {
        int chunk = tid + j * 256;
        sr[j] = chunk >> 3; scol[j] = (chunk & 7) * 8;
        agp[j] = aBase + (size_t)sr[j] * lda + scol[j];
        bgp[j] = bBase + (size_t)sr[j] * ldb + scol[j];
    }

    #pragma unroll
    for (int j = 0; j < 4; j++) {
        cp16(&As[0][sr[j]][scol[j]], agp[j]);
        cp16(&Bs[0][sr[j]][scol[j]], bgp[j]);
    }
    CP_COMMIT();
    CP_WAIT0();
    __syncthreads();

    const int NK = EMBED / 64;
    for (int it = 0; it < NK; it++) {
        const int buf = it & 1;
        if (it + 1 < NK) {
            const int kc = (it + 1) * 64;
            #pragma unroll
            for (int j = 0; j < 4; j++) {
                cp16(&As[buf ^ 1][sr[j]][scol[j]], agp[j] + kc);
                cp16(&Bs[buf ^ 1][sr[j]][scol[j]], bgp[j] + kc);
            }
            CP_COMMIT();
        }

        #pragma unroll
        for (int ks = 0; ks < 4; ks++) {
            const int k0 = ks * 16 + fk;
            uint32_t a[2][4], b[4][4];
            #pragma unroll
            for (int mi = 0; mi < 2; mi++)
                ldsm4(a[mi], &As[buf][wm * 32 + mi * 16 + fr][k0]);
            #pragma unroll
            for (int np = 0; np < 4; np++)
                ldsm4(b[np], &Bs[buf][wn * 64 + np * 16 + fr][k0]);
            #pragma unroll
            for (int np = 0; np < 4; np++) {
                #pragma unroll
                for (int mi = 0; mi < 2; mi++) {
                    mma16(acc.c[mi][2 * np    ], a[mi][0], a[mi][1], a[mi][2], a[mi][3],
                          b[np][0], b[np][2]);
                    mma16(acc.c[mi][2 * np + 1], a[mi][0], a[mi][1], a[mi][2], a[mi][3],
                          b[np][1], b[np][3]);
                }
            }
        }

        if (it + 1 < NK) CP_WAIT0();
        __syncthreads();
    }
}

// ============================================================================
// Kernel 1: QKV GEMM (fp16) -> fp16 Q/K [B,H,S,D] (Q scaled by log2e/8),
// V [B,H,D,S].
// ============================================================================
__global__ __launch_bounds__(256, 2) void qkv_kernel()
{
    const int n0 = blockIdx.x * 128;
    const int m0 = blockIdx.y * 128;

    GemmAcc acc;
    #pragma unroll
    for (int mi = 0; mi < 2; mi++)
        #pragma unroll
        for (int ni = 0; ni < 8; ni++)
            #pragma unroll
            for (int e = 0; e < 4; e++) acc.c[mi][ni][e] = 0.0f;

    gemm128h(acc, g_xh + (size_t)m0 * EMBED, g_wqkvh + (size_t)n0 * EMBED,
             EMBED, EMBED);

    const int lane = threadIdx.x & 31;
    const int warp = threadIdx.x >> 5;
    const int g    = lane >> 2;
    const int t4   = lane & 3;
    const int wm   = warp & 3;
    const int wn   = warp >> 2;

    const int mat = n0 >> 10;
    const int b   = m0 >> 11;
    const int s0l = m0 & 2047;
    const int h   = ((n0 & 1023) >> 6) + wn;
    const size_t bhOff = (size_t)(b * NHEADS + h);

    if (mat < 2) {
        __half* dst = ((mat == 0) ? g_qh : g_kh) + bhOff * SEQ * HEAD;
        const float scale = (mat == 0) ? (0.125f * LOG2E) : 1.0f;
        #pragma unroll
        for (int mi = 0; mi < 2; mi++) {
            int s0r = s0l + wm * 32 + mi * 16 + g;
            #pragma unroll
            for (int ni = 0; ni < 8; ni++) {
                int d = ni * 8 + t4 * 2;
                *(__half2*)(dst + (size_t)(s0r    ) * HEAD + d) =
                    __floats2half2_rn(acc.c[mi][ni][0] * scale, acc.c[mi][ni][1] * scale);
                *(__half2*)(dst + (size_t)(s0r + 8) * HEAD + d) =
                    __floats2half2_rn(acc.c[mi][ni][2] * scale, acc.c[mi][ni][3] * scale);
            }
        }
    } else {
        __half* dst = g_vh + bhOff * HEAD * SEQ;
        #pragma unroll
        for (int mi = 0; mi < 2; mi++) {
            int s0r = s0l + wm * 32 + mi * 16 + g;
            #pragma unroll
            for (int ni = 0; ni < 8; ni++) {
                int d = ni * 8 + t4 * 2;
                dst[(size_t)(d    ) * SEQ + s0r    ] = __float2half_rn(acc.c[mi][ni][0]);
                dst[(size_t)(d + 1) * SEQ + s0r    ] = __float2half_rn(acc.c[mi][ni][1]);
                dst[(size_t)(d    ) * SEQ + s0r + 8] = __float2half_rn(acc.c[mi][ni][2]);
                dst[(size_t)(d + 1) * SEQ + s0r + 8] = __float2half_rn(acc.c[mi][ni][3]);
            }
        }
    }
}

// ============================================================================
// Kernel 2: causal flash attention, fp16 mma, exp2 softmax.
// Heavy-first launch order: qt = 15 - blockIdx.x (heaviest q-tiles first).
// ============================================================================
__global__ __launch_bounds__(256, 2) void attn_kernel()
{
    extern __shared__ __half sh[];
    __half (*Qs)[72]     = (__half(*)[72])sh;                         // 128 x 72
    __half (*Ks)[32][72] = (__half(*)[32][72])(sh + 128 * 72);        // 3 x 32 x 72
    __half (*Vs)[64][40] = (__half(*)[64][40])(sh + 128 * 72 + 3 * 32 * 72); // 3 x 64 x 40

    const int bh = blockIdx.y;
    const int b  = bh >> 4;
    const int h  = bh & 15;
    const int qt = (SEQ / 128 - 1) - blockIdx.x;   // heavy blocks launch first
    const int q0 = qt * 128;

    const int tid  = threadIdx.x;
    const int lane = tid & 31;
    const int warp = tid >> 5;
    const int g    = lane >> 2;
    const int t4   = lane & 3;
    const int fr   = lane & 15;
    const int fk   = (lane >> 4) * 8;

    const __half* qp = g_qh + ((size_t)bh * SEQ + q0) * HEAD;
    const __half* kp = g_kh + (size_t)bh * SEQ * HEAD;
    const __half* vp = g_vh + (size_t)bh * HEAD * SEQ;

    // ---- stage Q, build 4 a-frags ----
    {
        #pragma unroll
        for (int j = 0; j < 4; j++) {
            int chunk = tid + j * 256;
            int r = chunk >> 3, c = (chunk & 7) * 8;
            cp16(&Qs[r][c], qp + (size_t)r * HEAD + c);
        }
        CP_COMMIT();
        CP_WAIT0();
        __syncthreads();
    }
    uint32_t qa[4][4];
    #pragma unroll
    for (int kf = 0; kf < 4; kf++)
        ldsm4(qa[kf], &Qs[warp * 16 + fr][kf * 16 + fk]);

    float o[8][4];
    #pragma unroll
    for (int dn = 0; dn < 8; dn++)
        #pragma unroll
        for (int e = 0; e < 4; e++) o[dn][e] = 0.0f;

    float m0 = -1e30f, m1 = -1e30f, l0 = 0.0f, l1 = 0.0f;

    const int nkt   = (qt + 1) * 4;
    const int row0b = q0 + warp * 16;
    const int qmaxw = row0b + 15;

    const int kr = tid >> 3, kc = (tid & 7) * 8;
    const int vr = tid >> 2, vc = (tid & 3) * 8;

    #pragma unroll
    for (int st = 0; st < 2; st++) {
        const int k0 = st * 32;
        cp16(&Ks[st][kr][kc], kp + (size_t)(k0 + kr) * HEAD + kc);
        cp16(&Vs[st][vr][vc], vp + (size_t)vr * SEQ + k0 + vc);
        CP_COMMIT();
    }

    int sc = 0;
    for (int kt = 0; kt < nkt; kt++) {
        const int k0 = kt * 32;

        CP_WAIT1();
        __syncthreads();

        if (kt + 2 < nkt) {
            int sp = sc + 2; if (sp >= 3) sp -= 3;
            const int kn = k0 + 64;
            cp16(&Ks[sp][kr][kc], kp + (size_t)(kn + kr) * HEAD + kc);
            cp16(&Vs[sp][vr][vc], vp + (size_t)vr * SEQ + kn + vc);
            CP_COMMIT();
        }

        if (k0 <= qmaxw) {
            // ---- S = Q K^T ----
            float s[4][4];
            #pragma unroll
            for (int nf = 0; nf < 4; nf++)
                #pragma unroll
                for (int e = 0; e < 4; e++) s[nf][e] = 0.0f;

            #pragma unroll
            for (int kf = 0; kf < 4; kf++) {
                #pragma unroll
                for (int np = 0; np < 2; np++) {
                    uint32_t bfr[4];
                    ldsm4(bfr, &Ks[sc][np * 16 + fr][kf * 16 + fk]);
                    mma16(s[2 * np    ], qa[kf][0], qa[kf][1], qa[kf][2], qa[kf][3],
                          bfr[0], bfr[2]);
                    mma16(s[2 * np + 1], qa[kf][0], qa[kf][1], qa[kf][2], qa[kf][3],
                          bfr[1], bfr[3]);
                }
            }

            // ---- causal mask (skipped on fully-unmasked tiles) ----
            const int r0 = row0b + g;
            const int r1 = r0 + 8;
            if (k0 + 31 > row0b) {
                #pragma unroll
                for (int nf = 0; nf < 4; nf++) {
                    int col0 = k0 + nf * 8 + t4 * 2;
                    if (col0     > r0) s[nf][0] = -1e30f;
                    if (col0 + 1 > r0) s[nf][1] = -1e30f;
                    if (col0     > r1) s[nf][2] = -1e30f;
                    if (col0 + 1 > r1) s[nf][3] = -1e30f;
                }
            }

            // ---- online softmax (exp2 domain) ----
            float rm0 = -1e30f, rm1 = -1e30f;
            #pragma unroll
            for (int nf = 0; nf < 4; nf++) {
                rm0 = fmaxf(rm0, fmaxf(s[nf][0], s[nf][1]));
                rm1 = fmaxf(rm1, fmaxf(s[nf][2], s[nf][3]));
            }
            rm0 = fmaxf(rm0, __shfl_xor_sync(0xffffffffu, rm0, 1));
            rm0 = fmaxf(rm0, __shfl_xor_sync(0xffffffffu, rm0, 2));
            rm1 = fmaxf(rm1, __shfl_xor_sync(0xffffffffu, rm1, 1));
            rm1 = fmaxf(rm1, __shfl_xor_sync(0xffffffffu, rm1, 2));

            float nm0 = fmaxf(m0, rm0), nm1 = fmaxf(m1, rm1);
            float sc0 = exp2f(m0 - nm0), sc1 = exp2f(m1 - nm1);

            float sum0 = 0.0f, sum1 = 0.0f;
            #pragma unroll
            for (int nf = 0; nf < 4; nf++) {
                s[nf][0] = exp2f(s[nf][0] - nm0);
                s[nf][1] = exp2f(s[nf][1] - nm0);
                s[nf][2] = exp2f(s[nf][2] - nm1);
                s[nf][3] = exp2f(s[nf][3] - nm1);
                sum0 += s[nf][0] + s[nf][1];
                sum1 += s[nf][2] + s[nf][3];
            }
            sum0 += __shfl_xor_sync(0xffffffffu, sum0, 1);
            sum0 += __shfl_xor_sync(0xffffffffu, sum0, 2);
            sum1 += __shfl_xor_sync(0xffffffffu, sum1, 1);
            sum1 += __shfl_xor_sync(0xffffffffu, sum1, 2);

            l0 = l0 * sc0 + sum0;  m0 = nm0;
            l1 = l1 * sc1 + sum1;  m1 = nm1;

            #pragma unroll
            for (int dn = 0; dn < 8; dn++) {
                o[dn][0] *= sc0; o[dn][1] *= sc0;
                o[dn][2] *= sc1; o[dn][3] *= sc1;
            }

            // ---- O += P V ----
            #pragma unroll
            for (int kf = 0; kf < 2; kf++) {
                uint32_t pa0 = h2u(__floats2half2_rn(s[2 * kf    ][0], s[2 * kf    ][1]));
                uint32_t pa1 = h2u(__floats2half2_rn(s[2 * kf    ][2], s[2 * kf    ][3]));
                uint32_t pa2 = h2u(__floats2half2_rn(s[2 * kf + 1][0], s[2 * kf + 1][1]));
                uint32_t pa3 = h2u(__floats2half2_rn(s[2 * kf + 1][2], s[2 * kf + 1][3]));
                #pragma unroll
                for (int np = 0; np < 4; np++) {
                    uint32_t bfr[4];
                    ldsm4(bfr, &Vs[sc][np * 16 + fr][kf * 16 + fk]);
                    mma16(o[2 * np    ], pa0, pa1, pa2, pa3, bfr[0], bfr[2]);
                    mma16(o[2 * np + 1], pa0, pa1, pa2, pa3, bfr[1], bfr[3]);
                }
            }
        }

        if (++sc == 3) sc = 0;
    }

    // ---- epilogue: normalize, write fp16 [B,S,H,D] ----
    const float inv0 = 1.0f / l0;
    const float inv1 = 1.0f / l1;
    const int r0 = q0 + warp * 16 + g;
    __half* ob = g_attnh + (size_t)b * SEQ * EMBED + (size_t)h * HEAD;
    #pragma unroll
    for (int dn = 0; dn < 8; dn++) {
        int d = dn * 8 + t4 * 2;
        *(__half2*)(ob + (size_t)(r0    ) * EMBED + d) =
            __floats2half2_rn(o[dn][0] * inv0, o[dn][1] * inv0);
        *(__half2*)(ob + (size_t)(r0 + 8) * EMBED + d) =
            __floats2half2_rn(o[dn][2] * inv1, o[dn][3] * inv1);
    }
}

// ============================================================================
// Kernel 3: output projection (fp16, proven).
// ============================================================================
__global__ __launch_bounds__(256, 2) void proj_kernel(
    const float* __restrict__ bo,
    float* __restrict__ out)
{
    const int e0 = blockIdx.x * 128;
    const int m0 = blockIdx.y * 128;

    GemmAcc acc;
    #pragma unroll
    for (int mi = 0; mi < 2; mi++)
        #pragma unroll
        for (int ni = 0; ni < 8; ni++)
            #pragma unroll
            for (int e = 0; e < 4; e++) acc.c[mi][ni][e] = 0.0f;

    gemm128h(acc, g_attnh + (size_t)m0 * EMBED, g_woh + (size_t)e0 * EMBED,
             EMBED, EMBED);

    const int lane = threadIdx.x & 31;
    const int warp = threadIdx.x >> 5;
    const int g    = lane >> 2;
    const int t4   = lane & 3;
    const int wm   = warp & 3;
    const int wn   = warp >> 2;

    #pragma unroll
    for (int mi = 0; mi < 2; mi++) {
        int r0 = m0 + wm * 32 + mi * 16 + g;
        #pragma unroll
        for (int ni = 0; ni < 8; ni++) {
            int e = e0 + wn * 64 + ni * 8 + t4 * 2;
            out[(size_t)(r0    ) * EMBED + e    ] = acc.c[mi][ni][0] + bo[e];
            out[(size_t)(r0    ) * EMBED + e + 1] = acc.c[mi][ni][1] + bo[e + 1];
            out[(size_t)(r0 + 8) * EMBED + e    ] = acc.c[mi][ni][2] + bo[e];
            out[(size_t)(r0 + 8) * EMBED + e + 1] = acc.c[mi][ni][3] + bo[e + 1];
        }
    }
}

// ============================================================================
extern "C" void kernel_launch(void* const* d_in, const int* in_sizes, int n_in,
                              void* d_out, int out_size)
{
    const float* x  = (const float*)d_in[0];
    const float* Wq = (const float*)d_in[1];
    const float* Wk = (const float*)d_in[2];
    const float* Wv = (const float*)d_in[3];
    const float* Wo = (const float*)d_in[4];
    const float* bo = (const float*)d_in[5];
    float* out = (float*)d_out;

    (void)in_sizes; (void)n_in; (void)out_size;

    cudaFuncSetAttribute(qkv_kernel,  cudaFuncAttributeMaxDynamicSharedMemorySize, GEMM_SMEM);
    cudaFuncSetAttribute(attn_kernel, cudaFuncAttributeMaxDynamicSharedMemorySize, ATTN_SMEM);
    cudaFuncSetAttribute(proj_kernel, cudaFuncAttributeMaxDynamicSharedMemorySize, GEMM_SMEM);

    prep_kernel<<<PREP_BLOCKS, 256>>>(x, Wq, Wk, Wv, Wo);

    qkv_kernel<<<dim3(QKVN / 128, NTOK / 128), 256, GEMM_SMEM>>>();
    attn_kernel<<<dim3(SEQ / 128, BATCH * NHEADS), 256, ATTN_SMEM>>>();
    proj_kernel<<<dim3(EMBED / 128, NTOK / 128), 256, GEMM_SMEM>>>(bo, out);
}

// round 17
// speedup vs baseline: 1.6160x; 1.0324x over previous
#include <cuda_runtime.h>
#include <cuda_fp16.h>
#include <stdint.h>
#include <math.h>

#define BATCH  4
#define NHEADS 16
#define HEAD   64
#define SEQ    2048
#define EMBED  1024
#define QKVN   3072
#define NTOK   (BATCH * SEQ)   // 8192
#define HPAD   72              // half-row pad: 144B, ldmatrix phase conflict-free
#define LOG2E  1.44269504088896340736f

// ---------------- scratch (device globals: allocation-free) ----------------
__device__ __half g_qh[BATCH * NHEADS * SEQ * HEAD];  // [B,H,S,D] fp16, scaled by log2e/8
__device__ __half g_kh[BATCH * NHEADS * SEQ * HEAD];  // [B,H,S,D] fp16
__device__ __half g_vh[BATCH * NHEADS * HEAD * SEQ];  // [B,H,D,S] fp16 (transposed)
__device__ __half g_attnh[BATCH * SEQ * EMBED];       // [B,S,H*D] fp16
__device__ __half g_xh[NTOK * EMBED];                 // X fp16
__device__ __half g_wqkvh[QKVN * EMBED];              // packed [n][k] fp16
__device__ __half g_woh[EMBED * EMBED];               // Wo [e][f] fp16

// ---------------- helpers ----------------
__device__ __forceinline__ void mma16(float* c,
                                      uint32_t a0, uint32_t a1, uint32_t a2, uint32_t a3,
                                      uint32_t b0, uint32_t b1) {
    asm volatile(
        "mma.sync.aligned.m16n8k16.row.col.f32.f16.f16.f32 "
        "{%0,%1,%2,%3}, {%4,%5,%6,%7}, {%8,%9}, {%0,%1,%2,%3};"
        : "+f"(c[0]), "+f"(c[1]), "+f"(c[2]), "+f"(c[3])
        : "r"(a0), "r"(a1), "r"(a2), "r"(a3), "r"(b0), "r"(b1));
}

__device__ __forceinline__ void ldsm4(uint32_t* r, const void* p) {
    uint32_t a = (uint32_t)__cvta_generic_to_shared(p);
    asm volatile("ldmatrix.sync.aligned.m8n8.x4.shared.b16 {%0,%1,%2,%3}, [%4];"
                 : "=r"(r[0]), "=r"(r[1]), "=r"(r[2]), "=r"(r[3]) : "r"(a));
}

__device__ __forceinline__ void cp16(void* smem, const void* gmem) {
    uint32_t sa = (uint32_t)__cvta_generic_to_shared(smem);
    asm volatile("cp.async.cg.shared.global [%0], [%1], 16;" :: "r"(sa), "l"(gmem));
}
#define CP_COMMIT() asm volatile("cp.async.commit_group;")
#define CP_WAIT0()  asm volatile("cp.async.wait_group 0;")
#define CP_WAIT1()  asm volatile("cp.async.wait_group 1;")

__device__ __forceinline__ uint32_t h2u(__half2 h) { return *(uint32_t*)&h; }

// smem sizes (bytes)
#define GEMM_SMEM (2 * 2 * 128 * HPAD * 2)                           // 73728
#define ATTN_SMEM ((128 * 72 + 3 * 32 * 72 + 3 * 64 * 40) * 2)      // 47616

// ============================================================================
// Prep: merged kernel.
// Blocks [0, NTOK): x->fp16.
// Blocks [NTOK, NTOK+3072): packw via coalesced 32x32 smem transpose.
// Blocks [NTOK+3072, +1024): Wo->fp16.
// ============================================================================
#define PACKW_BLOCKS 3072
#define PREP_BLOCKS  (NTOK + PACKW_BLOCKS + EMBED * EMBED / 1024)

__global__ __launch_bounds__(256) void prep_kernel(
    const float* __restrict__ x,
    const float* __restrict__ Wq, const float* __restrict__ Wk,
    const float* __restrict__ Wv, const float* __restrict__ Wo)
{
    const int blk = blockIdx.x;
    if (blk < NTOK) {   // x2h
        int i = (blk * 256 + threadIdx.x) * 4;
        float4 v = *(const float4*)(x + i);
        *(__half2*)(g_xh + i)     = __floats2half2_rn(v.x, v.y);
        *(__half2*)(g_xh + i + 2) = __floats2half2_rn(v.z, v.w);
    } else if (blk < NTOK + PACKW_BLOCKS) {
        // packw transpose: W[h][k][d] -> g_wqkvh[mat*1024 + h*64 + d][k]
        __shared__ __half t[32][33];
        int bi  = blk - NTOK;               // 0..3071
        int mat = bi >> 10;                 // /1024
        int rem = bi & 1023;
        int h   = rem >> 6;                 // /64
        int r2  = rem & 63;
        int kt  = r2 >> 1;                  // 0..31 (k tile of 32)
        int dt  = r2 & 1;                   // 0..1  (d tile of 32)
        int k0 = kt * 32, d0 = dt * 32;

        const float* w = (mat == 0) ? Wq : ((mat == 1) ? Wk : Wv);
        const float* wb = w + ((size_t)h * EMBED) * HEAD;

        int tx = threadIdx.x & 31;          // d within tile (read) / k (write)
        int ty = threadIdx.x >> 5;          // 0..7
        #pragma unroll
        for (int j = 0; j < 4; j++) {
            int kk = ty + j * 8;
            t[kk][tx] = __float2half_rn(wb[(size_t)(k0 + kk) * HEAD + d0 + tx]);
        }
        __syncthreads();
        __half* dst = g_wqkvh + ((size_t)(mat * 1024 + h * 64 + d0)) * EMBED + k0;
        #pragma unroll
        for (int j = 0; j < 4; j++) {
            int dd = ty + j * 8;
            dst[(size_t)dd * EMBED + tx] = t[tx][dd];
        }
    } else {   // wo2h
        int i = ((blk - NTOK - PACKW_BLOCKS) * 256 + threadIdx.x) * 4;
        float4 v = *(const float4*)(Wo + i);
        *(__half2*)(g_woh + i)     = __floats2half2_rn(v.x, v.y);
        *(__half2*)(g_woh + i + 2) = __floats2half2_rn(v.z, v.w);
    }
}

// ============================================================================
// fp16 GEMM body (proven): C[128x128] = A[128xK] * B^T.
// ============================================================================
struct GemmAcc { float c[2][8][4]; };

__device__ __forceinline__ void gemm128h(
    GemmAcc& acc,
    const __half* __restrict__ aBase,
    const __half* __restrict__ bBase,
    int lda, int ldb)
{
    extern __shared__ __half sh[];
    __half (*As)[128][HPAD] = (__half(*)[128][HPAD])sh;
    __half (*Bs)[128][HPAD] = (__half(*)[128][HPAD])(sh + 2 * 128 * HPAD);

    const int tid  = threadIdx.x;
    const int lane = tid & 31;
    const int warp = tid >> 5;
    const int wm   = warp & 3;
    const int wn   = warp >> 2;
    const int fr   = lane & 15;
    const int fk   = (lane >> 4) * 8;

    int sr[4], scol[4];
    const __half* agp[4];
    const __half* bgp[4];
    #pragma unroll
    for (int j = 0; j < 4; j++) {
        int chunk = tid + j * 256;
        sr[j] = chunk >> 3; scol[j] = (chunk & 7) * 8;
        agp[j] = aBase + (size_t)sr[j] * lda + scol[j];
        bgp[j] = bBase + (size_t)sr[j] * ldb + scol[j];
    }

    #pragma unroll
    for (int j = 0; j < 4; j++) {
        cp16(&As[0][sr[j]][scol[j]], agp[j]);
        cp16(&Bs[0][sr[j]][scol[j]], bgp[j]);
    }
    CP_COMMIT();
    CP_WAIT0();
    __syncthreads();

    const int NK = EMBED / 64;
    for (int it = 0; it < NK; it++) {
        const int buf = it & 1;
        if (it + 1 < NK) {
            const int kc = (it + 1) * 64;
            #pragma unroll
            for (int j = 0; j < 4; j++) {
                cp16(&As[buf ^ 1][sr[j]][scol[j]], agp[j] + kc);
                cp16(&Bs[buf ^ 1][sr[j]][scol[j]], bgp[j] + kc);
            }
            CP_COMMIT();
        }

        #pragma unroll
        for (int ks = 0; ks < 4; ks++) {
            const int k0 = ks * 16 + fk;
            uint32_t a[2][4], b[4][4];
            #pragma unroll
            for (int mi = 0; mi < 2; mi++)
                ldsm4(a[mi], &As[buf][wm * 32 + mi * 16 + fr][k0]);
            #pragma unroll
            for (int np = 0; np < 4; np++)
                ldsm4(b[np], &Bs[buf][wn * 64 + np * 16 + fr][k0]);
            #pragma unroll
            for (int np = 0; np < 4; np++) {
                #pragma unroll
                for (int mi = 0; mi < 2; mi++) {
                    mma16(acc.c[mi][2 * np    ], a[mi][0], a[mi][1], a[mi][2], a[mi][3],
                          b[np][0], b[np][2]);
                    mma16(acc.c[mi][2 * np + 1], a[mi][0], a[mi][1], a[mi][2], a[mi][3],
                          b[np][1], b[np][3]);
                }
            }
        }

        if (it + 1 < NK) CP_WAIT0();
        __syncthreads();
    }
}

// ============================================================================
// Kernel 1: QKV GEMM (fp16) -> fp16 Q/K [B,H,S,D] (Q scaled by log2e/8),
// V [B,H,D,S].
// ============================================================================
__global__ __launch_bounds__(256, 2) void qkv_kernel()
{
    const int n0 = blockIdx.x * 128;
    const int m0 = blockIdx.y * 128;

    GemmAcc acc;
    #pragma unroll
    for (int mi = 0; mi < 2; mi++)
        #pragma unroll
        for (int ni = 0; ni < 8; ni++)
            #pragma unroll
            for (int e = 0; e < 4; e++) acc.c[mi][ni][e] = 0.0f;

    gemm128h(acc, g_xh + (size_t)m0 * EMBED, g_wqkvh + (size_t)n0 * EMBED,
             EMBED, EMBED);

    const int lane = threadIdx.x & 31;
    const int warp = threadIdx.x >> 5;
    const int g    = lane >> 2;
    const int t4   = lane & 3;
    const int wm   = warp & 3;
    const int wn   = warp >> 2;

    const int mat = n0 >> 10;
    const int b   = m0 >> 11;
    const int s0l = m0 & 2047;
    const int h   = ((n0 & 1023) >> 6) + wn;
    const size_t bhOff = (size_t)(b * NHEADS + h);

    if (mat < 2) {
        __half* dst = ((mat == 0) ? g_qh : g_kh) + bhOff * SEQ * HEAD;
        const float scale = (mat == 0) ? (0.125f * LOG2E) : 1.0f;
        #pragma unroll
        for (int mi = 0; mi < 2; mi++) {
            int s0r = s0l + wm * 32 + mi * 16 + g;
            #pragma unroll
            for (int ni = 0; ni < 8; ni++) {
                int d = ni * 8 + t4 * 2;
                *(__half2*)(dst + (size_t)(s0r    ) * HEAD + d) =
                    __floats2half2_rn(acc.c[mi][ni][0] * scale, acc.c[mi][ni][1] * scale);
                *(__half2*)(dst + (size_t)(s0r + 8) * HEAD + d) =
                    __floats2half2_rn(acc.c[mi][ni][2] * scale, acc.c[mi][ni][3] * scale);
            }
        }
    } else {
        __half* dst = g_vh + bhOff * HEAD * SEQ;
        #pragma unroll
        for (int mi = 0; mi < 2; mi++) {
            int s0r = s0l + wm * 32 + mi * 16 + g;
            #pragma unroll
            for (int ni = 0; ni < 8; ni++) {
                int d = ni * 8 + t4 * 2;
                dst[(size_t)(d    ) * SEQ + s0r    ] = __float2half_rn(acc.c[mi][ni][0]);
                dst[(size_t)(d + 1) * SEQ + s0r    ] = __float2half_rn(acc.c[mi][ni][1]);
                dst[(size_t)(d    ) * SEQ + s0r + 8] = __float2half_rn(acc.c[mi][ni][2]);
                dst[(size_t)(d + 1) * SEQ + s0r + 8] = __float2half_rn(acc.c[mi][ni][3]);
            }
        }
    }
}

// ============================================================================
// Kernel 2: causal flash attention, fp16 mma, exp2 softmax, deferred l-reduce.
// Heavy-first launch order.  BM=128, BN=32, D=64.  3-stage cp.async ring.
// ============================================================================
__global__ __launch_bounds__(256, 2) void attn_kernel()
{
    extern __shared__ __half sh[];
    __half (*Qs)[72]     = (__half(*)[72])sh;                         // 128 x 72
    __half (*Ks)[32][72] = (__half(*)[32][72])(sh + 128 * 72);        // 3 x 32 x 72
    __half (*Vs)[64][40] = (__half(*)[64][40])(sh + 128 * 72 + 3 * 32 * 72); // 3 x 64 x 40

    const int bh = blockIdx.y;
    const int b  = bh >> 4;
    const int h  = bh & 15;
    const int qt = (SEQ / 128 - 1) - blockIdx.x;   // heavy blocks launch first
    const int q0 = qt * 128;

    const int tid  = threadIdx.x;
    const int lane = tid & 31;
    const int warp = tid >> 5;
    const int g    = lane >> 2;
    const int t4   = lane & 3;
    const int fr   = lane & 15;
    const int fk   = (lane >> 4) * 8;

    const __half* qp = g_qh + ((size_t)bh * SEQ + q0) * HEAD;
    const __half* kp = g_kh + (size_t)bh * SEQ * HEAD;
    const __half* vp = g_vh + (size_t)bh * HEAD * SEQ;

    // ---- stage Q, build 4 a-frags ----
    {
        #pragma unroll
        for (int j = 0; j < 4; j++) {
            int chunk = tid + j * 256;
            int r = chunk >> 3, c = (chunk & 7) * 8;
            cp16(&Qs[r][c], qp + (size_t)r * HEAD + c);
        }
        CP_COMMIT();
        CP_WAIT0();
        __syncthreads();
    }
    uint32_t qa[4][4];
    #pragma unroll
    for (int kf = 0; kf < 4; kf++)
        ldsm4(qa[kf], &Qs[warp * 16 + fr][kf * 16 + fk]);

    float o[8][4];
    #pragma unroll
    for (int dn = 0; dn < 8; dn++)
        #pragma unroll
        for (int e = 0; e < 4; e++) o[dn][e] = 0.0f;

    float m0 = -1e30f, m1 = -1e30f;
    float l0 = 0.0f, l1 = 0.0f;   // per-thread partial sums (reduced at epilogue)

    const int nkt   = (qt + 1) * 4;
    const int row0b = q0 + warp * 16;
    const int qmaxw = row0b + 15;

    const int kr = tid >> 3, kc = (tid & 7) * 8;
    const int vr = tid >> 2, vc = (tid & 3) * 8;

    #pragma unroll
    for (int st = 0; st < 2; st++) {
        const int k0 = st * 32;
        cp16(&Ks[st][kr][kc], kp + (size_t)(k0 + kr) * HEAD + kc);
        cp16(&Vs[st][vr][vc], vp + (size_t)vr * SEQ + k0 + vc);
        CP_COMMIT();
    }

    int sc = 0;
    for (int kt = 0; kt < nkt; kt++) {
        const int k0 = kt * 32;

        CP_WAIT1();
        __syncthreads();

        if (kt + 2 < nkt) {
            int sp = sc + 2; if (sp >= 3) sp -= 3;
            const int kn = k0 + 64;
            cp16(&Ks[sp][kr][kc], kp + (size_t)(kn + kr) * HEAD + kc);
            cp16(&Vs[sp][vr][vc], vp + (size_t)vr * SEQ + kn + vc);
            CP_COMMIT();
        }

        if (k0 <= qmaxw) {
            // ---- S = Q K^T ----
            float s[4][4];
            #pragma unroll
            for (int nf = 0; nf < 4; nf++)
                #pragma unroll
                for (int e = 0; e < 4; e++) s[nf][e] = 0.0f;

            #pragma unroll
            for (int kf = 0; kf < 4; kf++) {
                #pragma unroll
                for (int np = 0; np < 2; np++) {
                    uint32_t bfr[4];
                    ldsm4(bfr, &Ks[sc][np * 16 + fr][kf * 16 + fk]);
                    mma16(s[2 * np    ], qa[kf][0], qa[kf][1], qa[kf][2], qa[kf][3],
                          bfr[0], bfr[2]);
                    mma16(s[2 * np + 1], qa[kf][0], qa[kf][1], qa[kf][2], qa[kf][3],
                          bfr[1], bfr[3]);
                }
            }

            // ---- causal mask (skipped on fully-unmasked tiles) ----
            const int r0 = row0b + g;
            const int r1 = r0 + 8;
            if (k0 + 31 > row0b) {
                #pragma unroll
                for (int nf = 0; nf < 4; nf++) {
                    int col0 = k0 + nf * 8 + t4 * 2;
                    if (col0     > r0) s[nf][0] = -1e30f;
                    if (col0 + 1 > r0) s[nf][1] = -1e30f;
                    if (col0     > r1) s[nf][2] = -1e30f;
                    if (col0 + 1 > r1) s[nf][3] = -1e30f;
                }
            }

            // ---- online softmax (exp2 domain; max reduced, sum deferred) ----
            float rm0 = -1e30f, rm1 = -1e30f;
            #pragma unroll
            for (int nf = 0; nf < 4; nf++) {
                rm0 = fmaxf(rm0, fmaxf(s[nf][0], s[nf][1]));
                rm1 = fmaxf(rm1, fmaxf(s[nf][2], s[nf][3]));
            }
            rm0 = fmaxf(rm0, __shfl_xor_sync(0xffffffffu, rm0, 1));
            rm0 = fmaxf(rm0, __shfl_xor_sync(0xffffffffu, rm0, 2));
            rm1 = fmaxf(rm1, __shfl_xor_sync(0xffffffffu, rm1, 1));
            rm1 = fmaxf(rm1, __shfl_xor_sync(0xffffffffu, rm1, 2));

            float nm0 = fmaxf(m0, rm0), nm1 = fmaxf(m1, rm1);
            float sc0 = exp2f(m0 - nm0), sc1 = exp2f(m1 - nm1);

            float sum0 = 0.0f, sum1 = 0.0f;
            #pragma unroll
            for (int nf = 0; nf < 4; nf++) {
                s[nf][0] = exp2f(s[nf][0] - nm0);
                s[nf][1] = exp2f(s[nf][1] - nm0);
                s[nf][2] = exp2f(s[nf][2] - nm1);
                s[nf][3] = exp2f(s[nf][3] - nm1);
                sum0 += s[nf][0] + s[nf][1];
                sum1 += s[nf][2] + s[nf][3];
            }
            // no per-tile shuffle reduce: l stays thread-partial (m uniform per quad)
            l0 = l0 * sc0 + sum0;  m0 = nm0;
            l1 = l1 * sc1 + sum1;  m1 = nm1;

            #pragma unroll
            for (int dn = 0; dn < 8; dn++) {
                o[dn][0] *= sc0; o[dn][1] *= sc0;
                o[dn][2] *= sc1; o[dn][3] *= sc1;
            }

            // ---- O += P V ----
            #pragma unroll
            for (int kf = 0; kf < 2; kf++) {
                uint32_t pa0 = h2u(__floats2half2_rn(s[2 * kf    ][0], s[2 * kf    ][1]));
                uint32_t pa1 = h2u(__floats2half2_rn(s[2 * kf    ][2], s[2 * kf    ][3]));
                uint32_t pa2 = h2u(__floats2half2_rn(s[2 * kf + 1][0], s[2 * kf + 1][1]));
                uint32_t pa3 = h2u(__floats2half2_rn(s[2 * kf + 1][2], s[2 * kf + 1][3]));
                #pragma unroll
                for (int np = 0; np < 4; np++) {
                    uint32_t bfr[4];
                    ldsm4(bfr, &Vs[sc][np * 16 + fr][kf * 16 + fk]);
                    mma16(o[2 * np    ], pa0, pa1, pa2, pa3, bfr[0], bfr[2]);
                    mma16(o[2 * np + 1], pa0, pa1, pa2, pa3, bfr[1], bfr[3]);
                }
            }
        }

        if (++sc == 3) sc = 0;
    }

    // ---- epilogue: reduce partial l across the t4 quad, normalize, write ----
    l0 += __shfl_xor_sync(0xffffffffu, l0, 1);
    l0 += __shfl_xor_sync(0xffffffffu, l0, 2);
    l1 += __shfl_xor_sync(0xffffffffu, l1, 1);
    l1 += __shfl_xor_sync(0xffffffffu, l1, 2);
    const float inv0 = 1.0f / l0;
    const float inv1 = 1.0f / l1;
    const int r0 = q0 + warp * 16 + g;
    __half* ob = g_attnh + (size_t)b * SEQ * EMBED + (size_t)h * HEAD;
    #pragma unroll
    for (int dn = 0; dn < 8; dn++) {
        int d = dn * 8 + t4 * 2;
        *(__half2*)(ob + (size_t)(r0    ) * EMBED + d) =
            __floats2half2_rn(o[dn][0] * inv0, o[dn][1] * inv0);
        *(__half2*)(ob + (size_t)(r0 + 8) * EMBED + d) =
            __floats2half2_rn(o[dn][2] * inv1, o[dn][3] * inv1);
    }
}

// ============================================================================
// Kernel 3: output projection (fp16, proven).
// ============================================================================
__global__ __launch_bounds__(256, 2) void proj_kernel(
    const float* __restrict__ bo,
    float* __restrict__ out)
{
    const int e0 = blockIdx.x * 128;
    const int m0 = blockIdx.y * 128;

    GemmAcc acc;
    #pragma unroll
    for (int mi = 0; mi < 2; mi++)
        #pragma unroll
        for (int ni = 0; ni < 8; ni++)
            #pragma unroll
            for (int e = 0; e < 4; e++) acc.c[mi][ni][e] = 0.0f;

    gemm128h(acc, g_attnh + (size_t)m0 * EMBED, g_woh + (size_t)e0 * EMBED,
             EMBED, EMBED);

    const int lane = threadIdx.x & 31;
    const int warp = threadIdx.x >> 5;
    const int g    = lane >> 2;
    const int t4   = lane & 3;
    const int wm   = warp & 3;
    const int wn   = warp >> 2;

    #pragma unroll
    for (int mi = 0; mi < 2; mi++) {
        int r0 = m0 + wm * 32 + mi * 16 + g;
        #pragma unroll
        for (int ni = 0; ni < 8; ni++) {
            int e = e0 + wn * 64 + ni * 8 + t4 * 2;
            out[(size_t)(r0    ) * EMBED + e    ] = acc.c[mi][ni][0] + bo[e];
            out[(size_t)(r0    ) * EMBED + e + 1] = acc.c[mi][ni][1] + bo[e + 1];
            out[(size_t)(r0 + 8) * EMBED + e    ] = acc.c[mi][ni][2] + bo[e];
            out[(size_t)(r0 + 8) * EMBED + e + 1] = acc.c[mi][ni][3] + bo[e + 1];
        }
    }
}

// ============================================================================
extern "C" void kernel_launch(void* const* d_in, const int* in_sizes, int n_in,
                              void* d_out, int out_size)
{
    const float* x  = (const float*)d_in[0];
    const float* Wq = (const float*)d_in[1];
    const float* Wk = (const float*)d_in[2];
    const float* Wv = (const float*)d_in[3];
    const float* Wo = (const float*)d_in[4];
    const float* bo = (const float*)d_in[5];
    float* out = (float*)d_out;

    (void)in_sizes; (void)n_in; (void)out_size;

    cudaFuncSetAttribute(qkv_kernel,  cudaFuncAttributeMaxDynamicSharedMemorySize, GEMM_SMEM);
    cudaFuncSetAttribute(attn_kernel, cudaFuncAttributeMaxDynamicSharedMemorySize, ATTN_SMEM);
    cudaFuncSetAttribute(proj_kernel, cudaFuncAttributeMaxDynamicSharedMemorySize, GEMM_SMEM);

    prep_kernel<<<PREP_BLOCKS, 256>>>(x, Wq, Wk, Wv, Wo);

    qkv_kernel<<<dim3(QKVN / 128, NTOK / 128), 256, GEMM_SMEM>>>();
    attn_kernel<<<dim3(SEQ / 128, BATCH * NHEADS), 256, ATTN_SMEM>>>();
    proj_kernel<<<dim3(EMBED / 128, NTOK / 128), 256, GEMM_SMEM>>>(bo, out);
}